// round 12
// baseline (speedup 1.0000x reference)
#include <cuda_runtime.h>
#include <cuda_fp16.h>
#include <math.h>

#define BSZ 2
#define HEADS 16
#define SEQ 4096
#define DH 64
#define DM 1024
#define MF 266
#define MPX 288
#define CHK 128
#define NC 32
#define BH 32
#define TOK (BH*SEQ)
#define ROWS (BSZ*SEQ)

#define NORMALIZER 0.35355339059327373f
#define DIAG_COEF 0.0625f
#define RATIO 0.061313933948496584f
#define KEPS 1e-4f
#define CEPS 1e-6f
#define KSCALE 256.0f
#define LOG2E 1.4426950408889634f
#define LOG2_SCALE_Q (-4.0276427f)
#define LOG2_SCALE_K ( 3.9723573f)
#define KEPS_Q 6.1313934e-6f
#define KEPS_K 1.5696367e-3f

// ---------------- static scratch ----------------
__device__ __half g_qh[(size_t)TOK*DH];
__device__ __half g_kh[(size_t)TOK*DH];
__device__ __half g_vh[(size_t)TOK*DH];
__device__ __half g_qp[(size_t)TOK*MPX];
__device__ __half g_kp[(size_t)TOK*MPX];
__device__ __half g_csh[(size_t)BH*NC*MPX*DH];
__device__ __half g_zsh[(size_t)BH*NC*MPX];
__device__ __half g_attn[(size_t)ROWS*DM];
__device__ __half g_projh[384*DH];
__device__ __half g_xh[(size_t)ROWS*DM];
__device__ __half g_wh3[(size_t)3*DM*DM];
__device__ __half g_who[(size_t)DM*DM];
__device__ unsigned int g_kmax_bits;

__device__ __forceinline__ unsigned int enc_f(float f){
    unsigned int u = __float_as_uint(f);
    return (u & 0x80000000u) ? ~u : (u | 0x80000000u);
}
__device__ __forceinline__ float dec_f(unsigned int u){
    return (u & 0x80000000u) ? __uint_as_float(u & 0x7fffffffu)
                             : __uint_as_float(~u);
}
__device__ __forceinline__ unsigned sptr(const void* p){
    return (unsigned)__cvta_generic_to_shared(p);
}
__device__ __forceinline__ float ex2f(float x){
    float r; asm("ex2.approx.ftz.f32 %0, %1;" : "=f"(r) : "f"(x)); return r;
}
#define CP16(dst,src) asm volatile("cp.async.cg.shared.global [%0], [%1], 16;"::"r"(dst),"l"(src))
#define CPCOMMIT() asm volatile("cp.async.commit_group;")
#define CPWAIT1() asm volatile("cp.async.wait_group 1;")
#define CPWAIT0() asm volatile("cp.async.wait_group 0;")
#define LDM4(r0,r1,r2,r3,addr) \
    asm volatile("ldmatrix.sync.aligned.m8n8.x4.shared.b16 {%0,%1,%2,%3}, [%4];" \
        :"=r"(r0),"=r"(r1),"=r"(r2),"=r"(r3):"r"(addr))
#define LDM2(r0,r1,addr) \
    asm volatile("ldmatrix.sync.aligned.m8n8.x2.shared.b16 {%0,%1}, [%2];" \
        :"=r"(r0),"=r"(r1):"r"(addr))
#define LDM4T(r0,r1,r2,r3,addr) \
    asm volatile("ldmatrix.sync.aligned.m8n8.x4.trans.shared.b16 {%0,%1,%2,%3}, [%4];" \
        :"=r"(r0),"=r"(r1),"=r"(r2),"=r"(r3):"r"(addr))
#define LDM2T(r0,r1,addr) \
    asm volatile("ldmatrix.sync.aligned.m8n8.x2.trans.shared.b16 {%0,%1}, [%2];" \
        :"=r"(r0),"=r"(r1):"r"(addr))
#define MMA16(acc,a0,a1,a2,a3,b0,b1) \
    asm volatile("mma.sync.aligned.m16n8k16.row.col.f32.f16.f16.f32 " \
        "{%0,%1,%2,%3},{%4,%5,%6,%7},{%8,%9},{%0,%1,%2,%3};" \
        :"+f"(acc[0]),"+f"(acc[1]),"+f"(acc[2]),"+f"(acc[3]) \
        :"r"(a0),"r"(a1),"r"(a2),"r"(a3),"r"(b0),"r"(b1))

// ================= fp16 GEMM core =================
#define H_ISSUE(t,Abase,Bbase,Ksz) { int s_=(t)%3; \
    __half* As_=smh+s_*8192; __half* Bs_=As_+4096; \
    const __half* Ag_=(Abase)+(size_t)(t)*32; \
    const __half* Bg_=(Bbase)+(size_t)(t)*32; \
    _Pragma("unroll") for(int h=0;h<2;h++){ \
      int id=tid+h*256; int row=id>>2, cc=id&3; \
      unsigned sw=(unsigned)((cc^((row>>1)&3))*16); \
      CP16(sptr((char*)As_+row*64+sw), Ag_+(size_t)row*(Ksz)+cc*8); \
      CP16(sptr((char*)Bs_+row*64+sw), Bg_+(size_t)row*(Ksz)+cc*8); } \
    CPCOMMIT(); }

#define HGEMM_CORE(Abase,Bbase,Ksz,kt) \
    H_ISSUE(0,Abase,Bbase,Ksz); \
    if ((kt)>1) H_ISSUE(1,Abase,Bbase,Ksz); \
    for (int t=0;t<(kt);t++){ \
        if (t+1<(kt)) CPWAIT1(); else CPWAIT0(); \
        __syncthreads(); \
        __half* As = smh + (t%3)*8192; \
        __half* Bs = As + 4096; \
        _Pragma("unroll") \
        for (int k16=0;k16<2;k16++){ \
            unsigned a[4][4]; \
            _Pragma("unroll") \
            for (int mf=0;mf<4;mf++){ \
                int row = wm + mf*16 + lrow; \
                int qd = 2*k16 + lco; \
                unsigned ad = sptr((char*)As + row*64 + ((qd^((row>>1)&3))*16)); \
                LDM4(a[mf][0],a[mf][1],a[mf][2],a[mf][3],ad); \
            } \
            unsigned b[4][2]; \
            _Pragma("unroll") \
            for (int p=0;p<2;p++){ \
                int row = wn + p*16 + lrow; \
                int qd = 2*k16 + lco; \
                unsigned ad = sptr((char*)Bs + row*64 + ((qd^((row>>1)&3))*16)); \
                unsigned r0,r1,r2,r3; LDM4(r0,r1,r2,r3,ad); \
                b[2*p][0]=r0; b[2*p+1][0]=r1; b[2*p][1]=r2; b[2*p+1][1]=r3; \
            } \
            _Pragma("unroll") \
            for (int mf=0;mf<4;mf++) \
                _Pragma("unroll") \
                for (int nf=0;nf<4;nf++) \
                    MMA16(acc[mf][nf],a[mf][0],a[mf][1],a[mf][2],a[mf][3], \
                          b[nf][0],b[nf][1]); \
        } \
        __syncthreads(); \
        if (t+2<(kt)) H_ISSUE(t+2,Abase,Bbase,Ksz); \
    }

#define GEMM_PREAMBLE() \
    const int tid=threadIdx.x, lane=tid&31, wid=tid>>5; \
    const int wm=(wid&1)*64, wn=(wid>>1)*32; \
    const int qr=lane>>2, qc=lane&3; \
    const int lrow=(lane&7)+(lane&8); \
    const int lco=lane>>4; \
    float acc[4][4][4]; \
    _Pragma("unroll") \
    for(int i=0;i<4;i++) \
        _Pragma("unroll") \
        for(int j=0;j<4;j++){acc[i][j][0]=0;acc[i][j][1]=0;acc[i][j][2]=0;acc[i][j][3]=0;}

// ---------------- fused QKV GEMM ---------------------------------------------
__global__ __launch_bounds__(256,2)
void hgemm_qkv(const float* __restrict__ bq, const float* __restrict__ bk,
               const float* __restrict__ bv)
{
    __shared__ __half smh[3*8192];
    const int m0=blockIdx.y*128, n0=blockIdx.x*128;
    GEMM_PREAMBLE();
    const __half* Abase = g_xh  + (size_t)m0*DM;
    const __half* Bbase = g_wh3 + (size_t)n0*DM;
    HGEMM_CORE(Abase, Bbase, DM, 32);

    #pragma unroll
    for (int mf=0;mf<4;mf++){
        int tr0 = m0 + wm + mf*16 + qr;
        int b0 = tr0 >> 12, n_ = tr0 & 4095;
        #pragma unroll
        for (int nf=0;nf<4;nf++){
            int col = n0 + wn + nf*8 + qc*2;
            int sel = col >> 10;
            int c1  = col & 1023;
            int h = c1 >> 6, d = c1 & 63;
            const float* bias = (sel==0) ? bq : (sel==1) ? bk : bv;
            __half* dst = (sel==0) ? g_qh : (sel==1) ? g_kh : g_vh;
            float bb0 = bias[c1], bb1 = bias[c1+1];
            size_t base0 = (((size_t)(b0*HEADS+h))*SEQ + n_)*DH + d;
            size_t base1 = (((size_t)(b0*HEADS+h))*SEQ + n_ + 8)*DH + d;
            *(__half2*)(dst + base0) = __floats2half2_rn(acc[mf][nf][0]+bb0, acc[mf][nf][1]+bb1);
            *(__half2*)(dst + base1) = __floats2half2_rn(acc[mf][nf][2]+bb0, acc[mf][nf][3]+bb1);
        }
    }
}

// ---------------- output projection GEMM -------------------------------------
__global__ __launch_bounds__(256,2)
void hgemm_out(float* __restrict__ C, const float* __restrict__ bias)
{
    __shared__ __half smh[3*8192];
    const int m0=blockIdx.y*128, n0=blockIdx.x*128;
    GEMM_PREAMBLE();
    const __half* Abase = g_attn + (size_t)m0*DM;
    const __half* Bbase = g_who  + (size_t)n0*DM;
    HGEMM_CORE(Abase, Bbase, DM, 32);

    #pragma unroll
    for (int mf=0;mf<4;mf++){
        #pragma unroll
        for (int nf=0;nf<4;nf++){
            int row = m0 + wm + mf*16 + qr;
            int col = n0 + wn + nf*8 + qc*2;
            float b0 = bias[col], b1 = bias[col+1];
            float2 v0; v0.x=acc[mf][nf][0]+b0; v0.y=acc[mf][nf][1]+b1;
            float2 v1; v1.x=acc[mf][nf][2]+b0; v1.y=acc[mf][nf][3]+b1;
            *(float2*)(C + (size_t)row*DM + col)     = v0;
            *(float2*)(C + (size_t)(row+8)*DM + col) = v1;
        }
    }
}

// ---------------- fused feature GEMM (wide tile), q fused / k raw+max --------
// CTA: 128 rows x 288 cols, K=64. 2 m-warps x 4 n-warps, warp tile 64x72.
#define FQ_SMEM (26624*2 + 128*4*4 + 128*4)
__global__ __launch_bounds__(256,1)
void hgemm_feat2()
{
    extern __shared__ __half sh_dyn[];
    __half* A0 = sh_dyn;
    __half* A1 = sh_dyn + 4096;
    __half* B0 = sh_dyn + 8192;
    __half* B1 = sh_dyn + 17408;
    float* rowmax4 = (float*)(sh_dyn + 26624);
    float* diagb   = rowmax4 + 128*4;

    const int z = blockIdx.y;               // 0: q (fused), 1: k (raw + max)
    const __half* src = z ? g_kh : g_qh;
    const int tid=threadIdx.x, lane=tid&31, wid=tid>>5;
    const int wm=(wid&1)*64, wn=(wid>>1)*72;
    const int qr=lane>>2, qc=lane&3;
    const int lrow=(lane&7)+(lane&8);
    const int lco=lane>>4;
    const size_t tok0 = (size_t)blockIdx.x*128;

    #pragma unroll
    for (int j=0;j<2;j++){
        int cid = tid + j*256; int row = cid>>2, cc = cid&3;
        unsigned sw = (unsigned)((cc^((row>>1)&3))*16);
        CP16(sptr((char*)A0 + row*64 + sw), src + (tok0+row)*DH + cc*8);
        CP16(sptr((char*)A1 + row*64 + sw), src + (tok0+row)*DH + 32 + cc*8);
    }
    #pragma unroll
    for (int j=0;j<5;j++){
        int cid = tid + j*256;
        if (cid < 1152){
            int row = cid>>2, cc = cid&3;
            unsigned sw = (unsigned)((cc^((row>>1)&3))*16);
            CP16(sptr((char*)B0 + row*64 + sw), g_projh + row*DH + cc*8);
            CP16(sptr((char*)B1 + row*64 + sw), g_projh + row*DH + 32 + cc*8);
        }
    }
    CPCOMMIT(); CPWAIT0();
    __syncthreads();

    if (z==0 && tid < 128){
        float s = 0.f;
        #pragma unroll
        for (int st=0; st<2; st++){
            const char* Ab = (const char*)(st ? A1 : A0);
            #pragma unroll
            for (int cc=0;cc<4;cc++){
                uint4 u = *(const uint4*)(Ab + tid*64 + ((cc^((tid>>1)&3))*16));
                const __half2* hp = (const __half2*)&u;
                #pragma unroll
                for (int p=0;p<4;p++){
                    float2 f = __half22float2(hp[p]);
                    s = fmaf(f.x,f.x,s); s = fmaf(f.y,f.y,s);
                }
            }
        }
        diagb[tid] = DIAG_COEF * s;
    }

    float acc[4][9][4];
    #pragma unroll
    for (int i=0;i<4;i++)
        #pragma unroll
        for (int j=0;j<9;j++){acc[i][j][0]=0;acc[i][j][1]=0;acc[i][j][2]=0;acc[i][j][3]=0;}

    #pragma unroll
    for (int k16=0;k16<4;k16++){
        __half* As = (k16<2) ? A0 : A1;
        __half* Bs = (k16<2) ? B0 : B1;
        int kk = k16 & 1;
        unsigned a[4][4];
        #pragma unroll
        for (int mf=0;mf<4;mf++){
            int row = wm + mf*16 + lrow;
            int qd = 2*kk + lco;
            unsigned ad = sptr((char*)As + row*64 + ((qd^((row>>1)&3))*16));
            LDM4(a[mf][0],a[mf][1],a[mf][2],a[mf][3],ad);
        }
        unsigned b[9][2];
        #pragma unroll
        for (int p=0;p<4;p++){
            int row = wn + p*16 + lrow;
            int qd = 2*kk + lco;
            unsigned ad = sptr((char*)Bs + row*64 + ((qd^((row>>1)&3))*16));
            unsigned r0,r1,r2,r3; LDM4(r0,r1,r2,r3,ad);
            b[2*p][0]=r0; b[2*p+1][0]=r1; b[2*p][1]=r2; b[2*p+1][1]=r3;
        }
        {
            int row8 = wn + 64 + (lane&7);
            int ch = 2*kk + ((lane>>3)&1);
            unsigned ad = sptr((char*)Bs + row8*64 + ((ch^((row8>>1)&3))*16));
            unsigned r0,r1; LDM2(r0,r1,ad);
            b[8][0]=r0; b[8][1]=r1;
        }
        #pragma unroll
        for (int mf=0;mf<4;mf++)
            #pragma unroll
            for (int nf=0;nf<9;nf++)
                MMA16(acc[mf][nf], a[mf][0],a[mf][1],a[mf][2],a[mf][3],
                      b[nf][0], b[nf][1]);
    }

    if (z){
        // k side: store raw kp + block max -> atomicMax
        float mx = -3.4e38f;
        #pragma unroll
        for (int mf=0;mf<4;mf++){
            #pragma unroll
            for (int h=0;h<2;h++){
                int row = wm + mf*16 + qr + 8*h;
                #pragma unroll
                for (int nf=0;nf<9;nf++){
                    int col = wn + nf*8 + qc*2;
                    float v0 = acc[mf][nf][2*h], v1 = acc[mf][nf][2*h+1];
                    *(__half2*)(g_kp + (tok0+row)*MPX + col) = __floats2half2_rn(v0, v1);
                    if (col   < MF) mx = fmaxf(mx, v0);
                    if (col+1 < MF) mx = fmaxf(mx, v1);
                }
            }
        }
        #pragma unroll
        for (int o=16;o;o>>=1) mx = fmaxf(mx, __shfl_xor_sync(0xffffffffu, mx, o));
        __syncthreads();
        if (lane==0) rowmax4[wid] = mx;
        __syncthreads();
        if (tid==0){
            float m = rowmax4[0];
            #pragma unroll
            for (int w=1;w<8;w++) m = fmaxf(m, rowmax4[w]);
            atomicMax(&g_kmax_bits, enc_f(m));
        }
        return;
    }

    // q side: rowmax + exp + store
    float pm[4][2];
    #pragma unroll
    for (int mf=0;mf<4;mf++){ pm[mf][0]=-3.4e38f; pm[mf][1]=-3.4e38f; }
    #pragma unroll
    for (int mf=0;mf<4;mf++)
        #pragma unroll
        for (int nf=0;nf<9;nf++){
            int col = wn + nf*8 + qc*2;
            if (col < MF){
                pm[mf][0] = fmaxf(pm[mf][0], acc[mf][nf][0]);
                pm[mf][1] = fmaxf(pm[mf][1], acc[mf][nf][2]);
            }
            if (col+1 < MF){
                pm[mf][0] = fmaxf(pm[mf][0], acc[mf][nf][1]);
                pm[mf][1] = fmaxf(pm[mf][1], acc[mf][nf][3]);
            }
        }
    #pragma unroll
    for (int o=1;o<4;o<<=1)
        #pragma unroll
        for (int mf=0;mf<4;mf++){
            pm[mf][0] = fmaxf(pm[mf][0], __shfl_xor_sync(0xffffffffu, pm[mf][0], o));
            pm[mf][1] = fmaxf(pm[mf][1], __shfl_xor_sync(0xffffffffu, pm[mf][1], o));
        }
    if (qc==0){
        #pragma unroll
        for (int mf=0;mf<4;mf++){
            rowmax4[(wm+mf*16+qr  )*4 + (wid>>1)] = pm[mf][0];
            rowmax4[(wm+mf*16+qr+8)*4 + (wid>>1)] = pm[mf][1];
        }
    }
    __syncthreads();

    #pragma unroll
    for (int mf=0;mf<4;mf++){
        #pragma unroll
        for (int h=0;h<2;h++){
            int row = wm + mf*16 + qr + 8*h;
            const float* rm = rowmax4 + row*4;
            float mx = fmaxf(fmaxf(rm[0],rm[1]), fmaxf(rm[2],rm[3]));
            float base = fmaf(-(diagb[row]+mx), LOG2E, LOG2_SCALE_Q);
            #pragma unroll
            for (int nf=0;nf<9;nf++){
                int col = wn + nf*8 + qc*2;
                float w0 = (col   < MF) ? (ex2f(fmaf(acc[mf][nf][2*h  ], LOG2E, base)) + KEPS_Q) : 0.f;
                float w1 = (col+1 < MF) ? (ex2f(fmaf(acc[mf][nf][2*h+1], LOG2E, base)) + KEPS_Q) : 0.f;
                *(__half2*)(g_qp + (tok0+row)*MPX + col) = __floats2half2_rn(w0, w1);
            }
        }
    }
}

// ---------------- fused prep ----------------
#define N4_X (ROWS*DM/4)
#define N4_W (DM*DM/4)
#define N4_P (384*DH/4)
#define N4_ALL (N4_X + 4*N4_W + N4_P)
__global__ void prep_all(const float* __restrict__ x,  const float* __restrict__ Wq,
                         const float* __restrict__ Wk, const float* __restrict__ Wv,
                         const float* __restrict__ Wo, const float* __restrict__ proj)
{
    long i = (long)blockIdx.x*256 + threadIdx.x;
    if (i == 0) g_kmax_bits = 0u;
    if (i < N4_X){
        float4 v = ((const float4*)x)[i];
        ((__half2*)g_xh)[i*2]   = __floats2half2_rn(v.x, v.y);
        ((__half2*)g_xh)[i*2+1] = __floats2half2_rn(v.z, v.w);
        return;
    }
    i -= N4_X;
    if (i < 4L*N4_W){
        int w = (int)(i / N4_W); long j = i % N4_W;
        const float* src = (w==0)?Wq:(w==1)?Wk:(w==2)?Wv:Wo;
        __half* dst = (w<3) ? (g_wh3 + (size_t)w*DM*DM) : g_who;
        float4 v = ((const float4*)src)[j];
        ((__half2*)dst)[j*2]   = __floats2half2_rn(v.x, v.y);
        ((__half2*)dst)[j*2+1] = __floats2half2_rn(v.z, v.w);
        return;
    }
    i -= 4L*N4_W;
    if (i < N4_P){
        long e = i*4;
        #pragma unroll
        for (int j=0;j<4;j++){
            long m = (e+j)/DH, d = (e+j)%DH;
            g_projh[e+j] = (m < MF) ? __float2half(proj[m*DH+d]*NORMALIZER)
                                    : __float2half(0.f);
        }
    }
}

// ---------------- exp feature map for k (global max) -------------------------
__device__ __forceinline__ void unpack8(uint4 c, float* v){
    float2 t;
    t=__half22float2(*(__half2*)&c.x); v[0]=t.x; v[1]=t.y;
    t=__half22float2(*(__half2*)&c.y); v[2]=t.x; v[3]=t.y;
    t=__half22float2(*(__half2*)&c.z); v[4]=t.x; v[5]=t.y;
    t=__half22float2(*(__half2*)&c.w); v[6]=t.x; v[7]=t.y;
}
__device__ __forceinline__ uint4 pack8(const float* v){
    uint4 c;
    *(__half2*)&c.x = __floats2half2_rn(v[0],v[1]);
    *(__half2*)&c.y = __floats2half2_rn(v[2],v[3]);
    *(__half2*)&c.z = __floats2half2_rn(v[4],v[5]);
    *(__half2*)&c.w = __floats2half2_rn(v[6],v[7]);
    return c;
}
__global__ void feat_apply_k()
{
    int warp = threadIdx.x >> 5, lane = threadIdx.x & 31;
    size_t row = (size_t)blockIdx.x*8 + warp;
    float2 qq = __half22float2(((const __half2*)(g_kh + row*DH))[lane]);
    float s = qq.x*qq.x + qq.y*qq.y;
    #pragma unroll
    for (int o=16;o;o>>=1) s += __shfl_xor_sync(0xffffffffu, s, o);
    float diag = DIAG_COEF * s;

    __half* dd = g_kp + row*MPX;
    uint4 c0 = ((const uint4*)dd)[lane];
    uint4 c1 = make_uint4(0,0,0,0);
    bool act1 = lane < 4;
    if (act1) c1 = ((const uint4*)dd)[32 + lane];
    float v0[8], v1[8];
    unpack8(c0, v0); unpack8(c1, v1);

    float mx = dec_f(g_kmax_bits);
    const float base = fmaf(-(diag+mx), LOG2E, LOG2_SCALE_K);
    float w0[8], w1[8];
    #pragma unroll
    for (int j=0;j<8;j++) w0[j] = ex2f(fmaf(v0[j], LOG2E, base)) + KEPS_K;
    #pragma unroll
    for (int j=0;j<8;j++){
        int m = 256 + lane*8 + j;
        w1[j] = (m < MF) ? (ex2f(fmaf(v1[j], LOG2E, base)) + KEPS_K) : 0.f;
    }
    ((uint4*)dd)[lane] = pack8(w0);
    if (act1) ((uint4*)dd)[32 + lane] = pack8(w1);
}

// ---------------- chunk sums via fp16 MMA ------------------------------------
#define CS_SMEM ((128*296 + 128*72)*2)
extern __shared__ __half sh_dyn2[];
__global__ __launch_bounds__(256)
void chunk_sums_mma()
{
    __half* Kt = sh_dyn2;
    __half* Vt = sh_dyn2 + 128*296;
    const int tid=threadIdx.x, lane=tid&31, wid=tid>>5;
    const int blk=blockIdx.x;
    const size_t tok0=(size_t)blk*CHK;
    const int qr=lane>>2, qc=lane&3;

    #pragma unroll
    for (int j=0;j<18;j++){
        int cid = tid + j*256; int row = cid/36, c = cid%36;
        CP16(sptr(Kt + row*296 + c*8), g_kp + (tok0+row)*MPX + c*8);
    }
    #pragma unroll
    for (int j=0;j<4;j++){
        int cid = tid + j*256; int row = cid>>3, c = cid&7;
        CP16(sptr(Vt + row*72 + c*8), g_vh + (tok0+row)*DH + c*8);
    }
    CPCOMMIT(); CPWAIT0();
    __syncthreads();
    if (tid < 128){
        __half* vr = Vt + tid*72;
        vr[64] = __float2half(1.f);
        #pragma unroll
        for (int j=65;j<72;j++) vr[j] = __float2half(0.f);
    }
    __syncthreads();

    const int nfr = (wid<2) ? 3 : 2;
    int mfs[3]; mfs[0]=wid; mfs[1]=wid+8; mfs[2]=16+wid;
    float acc[3][9][4];
    #pragma unroll
    for(int i=0;i<3;i++)
        #pragma unroll
        for(int j=0;j<9;j++){acc[i][j][0]=0;acc[i][j][1]=0;acc[i][j][2]=0;acc[i][j][3]=0;}

    for (int ks=0;ks<8;ks++){
        int k0 = ks*16;
        int trow = k0 + (lane&7) + ((lane&16)>>1);
        unsigned bf[9][2];
        #pragma unroll
        for (int bi=0;bi<4;bi++){
            unsigned ad = sptr(Vt + trow*72 + bi*16 + (lane&8));
            unsigned r0,r1,r2,r3; LDM4T(r0,r1,r2,r3,ad);
            bf[2*bi][0]=r0; bf[2*bi][1]=r2; bf[2*bi+1][0]=r1; bf[2*bi+1][1]=r3;
        }
        {
            unsigned ad = sptr(Vt + (k0 + (lane&15))*72 + 64);
            unsigned r0,r1; LDM2T(r0,r1,ad);
            bf[8][0]=r0; bf[8][1]=r1;
        }
        for (int fi=0; fi<nfr; fi++){
            unsigned ad = sptr(Kt + trow*296 + mfs[fi]*16 + (lane&8));
            unsigned a0,a1,a2,a3; LDM4T(a0,a1,a2,a3,ad);
            #pragma unroll
            for (int nf=0;nf<9;nf++)
                MMA16(acc[fi][nf], a0,a1,a2,a3, bf[nf][0], bf[nf][1]);
        }
    }

    for (int fi=0; fi<nfr; fi++){
        int m0 = mfs[fi]*16;
        #pragma unroll
        for (int nf=0;nf<8;nf++){
            int col = nf*8 + qc*2;
            *(__half2*)(g_csh + ((size_t)blk*MPX + m0+qr)*DH + col)   = __floats2half2_rn(acc[fi][nf][0], acc[fi][nf][1]);
            *(__half2*)(g_csh + ((size_t)blk*MPX + m0+qr+8)*DH + col) = __floats2half2_rn(acc[fi][nf][2], acc[fi][nf][3]);
        }
        if (qc==0){
            g_zsh[(size_t)blk*MPX + m0+qr]   = __float2half(acc[fi][8][0]);
            g_zsh[(size_t)blk*MPX + m0+qr+8] = __float2half(acc[fi][8][2]);
        }
    }
}

// ---------------- parallel exclusive scan over chunks (uint2 width) ---------
__global__ __launch_bounds__(256)
void scan_par()
{
    int bh = blockIdx.y;
    if (blockIdx.x < 18){
        int l = blockIdx.x*256 + threadIdx.x;            // [0, 4608) of uint2
        uint2* base = (uint2*)(g_csh + (size_t)bh*NC*MPX*DH) + l;
        const int stride = MPX*DH/4;                     // 4608 uint2 per chunk
        float s0=0.f,s1=0.f,s2=0.f,s3=0.f;
        #pragma unroll
        for (int c=0;c<NC;c++){
            uint2 u = base[(size_t)c*stride];
            float2 t0 = __half22float2(*(__half2*)&u.x);
            float2 t1 = __half22float2(*(__half2*)&u.y);
            uint2 o;
            *(__half2*)&o.x = __floats2half2_rn(s0, s1);
            *(__half2*)&o.y = __floats2half2_rn(s2, s3);
            base[(size_t)c*stride] = o;
            s0 += t0.x; s1 += t0.y; s2 += t1.x; s3 += t1.y;
        }
    } else {
        if (threadIdx.x < 72){
            uint2* base = (uint2*)(g_zsh + (size_t)bh*NC*MPX) + threadIdx.x;
            const int stride = MPX/4;                    // 72 uint2 per chunk
            float s0=0.f,s1=0.f,s2=0.f,s3=0.f;
            #pragma unroll
            for (int c=0;c<NC;c++){
                uint2 u = base[(size_t)c*stride];
                float2 t0 = __half22float2(*(__half2*)&u.x);
                float2 t1 = __half22float2(*(__half2*)&u.y);
                uint2 o;
                *(__half2*)&o.x = __floats2half2_rn(s0, s1);
                *(__half2*)&o.y = __floats2half2_rn(s2, s3);
                base[(size_t)c*stride] = o;
                s0 += t0.x; s1 += t0.y; s2 += t1.x; s3 += t1.y;
            }
        }
    }
}

// ---------------- out_chunk via fp16 MMA --------------------------------------
#define OC_STAGE 10496
#define OC_VT 20992
#define OC_SMEM ((20992 + 128*72)*2)
__global__ __launch_bounds__(256)
void out_chunk_h()
{
    __half* Am = sh_dyn2;
    __half* Vt = sh_dyn2 + OC_VT;
    const int tid=threadIdx.x, lane=tid&31, wid=tid>>5;
    const int blk=blockIdx.x, bh=blk>>5, c=blk&31;
    const size_t tok0=(size_t)blk*CHK;
    const int qr=lane>>2, qc=lane&3;
    const int lrow=(lane&7)+(lane&8);
    const int lco=lane>>4;
    const __half ceps_h = __float2half(KSCALE*CEPS);

    #pragma unroll
    for (int j=0;j<4;j++){
        int cid = tid + j*256; int row = cid>>3, cc = cid&7;
        CP16(sptr(Vt + row*72 + cc*8), g_vh + (tok0+row)*DH + cc*8);
    }

    float accA[16][4];
    float accO[9][4];
    #pragma unroll
    for(int i=0;i<16;i++){accA[i][0]=0;accA[i][1]=0;accA[i][2]=0;accA[i][3]=0;}
    #pragma unroll
    for(int i=0;i<9;i++){accO[i][0]=0;accO[i][1]=0;accO[i][2]=0;accO[i][3]=0;}

#define OCH_ISSUE(t) { int s_=(t)&1; \
    __half* Qs_=sh_dyn2+s_*OC_STAGE; __half* Ks_=Qs_+4096; __half* Ss_=Qs_+8192; \
    _Pragma("unroll") for(int h=0;h<2;h++){ \
      int id=tid+h*256; int row=id>>2, cc=id&3; \
      unsigned sw=(unsigned)((cc^((row>>1)&3))*16); \
      CP16(sptr((char*)Qs_+row*64+sw), g_qp+(tok0+row)*MPX+(t)*32+cc*8); \
      CP16(sptr((char*)Ks_+row*64+sw), g_kp+(tok0+row)*MPX+(t)*32+cc*8); } \
    { int row=tid>>3, cc=tid&7; \
      CP16(sptr(Ss_+row*72+cc*8), g_csh+((size_t)blk*MPX+(t)*32+row)*DH+cc*8); } \
    if (tid<32){ __half* sr=Ss_+tid*72; sr[64]=g_zsh[(size_t)blk*MPX+(t)*32+tid]; \
      sr[65]=ceps_h; \
      _Pragma("unroll") for(int j=66;j<72;j++) sr[j]=__float2half(0.f); } \
    CPCOMMIT(); }

    OCH_ISSUE(0);
    for (int t=0;t<9;t++){
        if (t+1<9) OCH_ISSUE(t+1);
        if (t<8) CPWAIT1(); else CPWAIT0();
        __syncthreads();
        __half* Qs = sh_dyn2 + (t&1)*OC_STAGE;
        __half* Ks = Qs + 4096;
        __half* Ss = Qs + 8192;
        #pragma unroll
        for (int k16=0;k16<2;k16++){
            unsigned a[4];
            {
                int row = wid*16 + lrow;
                int qd = 2*k16 + lco;
                unsigned ad = sptr((char*)Qs + row*64 + ((qd^((row>>1)&3))*16));
                LDM4(a[0],a[1],a[2],a[3],ad);
            }
            #pragma unroll
            for (int p=0;p<8;p++){
                int row = p*16 + lrow;
                int qd = 2*k16 + lco;
                unsigned ad = sptr((char*)Ks + row*64 + ((qd^((row>>1)&3))*16));
                unsigned r0,r1,r2,r3; LDM4(r0,r1,r2,r3,ad);
                MMA16(accA[2*p],  a[0],a[1],a[2],a[3], r0, r2);
                MMA16(accA[2*p+1],a[0],a[1],a[2],a[3], r1, r3);
            }
            {
                int trow = k16*16 + (lane&7) + ((lane&16)>>1);
                unsigned bf[9][2];
                #pragma unroll
                for (int bi=0;bi<4;bi++){
                    unsigned ad = sptr(Ss + trow*72 + bi*16 + (lane&8));
                    unsigned r0,r1,r2,r3; LDM4T(r0,r1,r2,r3,ad);
                    bf[2*bi][0]=r0; bf[2*bi][1]=r2; bf[2*bi+1][0]=r1; bf[2*bi+1][1]=r3;
                }
                {
                    unsigned ad = sptr(Ss + (k16*16 + (lane&15))*72 + 64);
                    unsigned r0,r1; LDM2T(r0,r1,ad);
                    bf[8][0]=r0; bf[8][1]=r1;
                }
                #pragma unroll
                for (int nf=0;nf<9;nf++)
                    MMA16(accO[nf], a[0],a[1],a[2],a[3], bf[nf][0], bf[nf][1]);
            }
        }
        __syncthreads();
    }

    if (tid < 128){
        __half* vr = Vt + tid*72;
        vr[64] = __float2half(1.f);
        #pragma unroll
        for (int j=65;j<72;j++) vr[j] = __float2half(0.f);
    }
    #pragma unroll
    for (int nf=0;nf<16;nf++){
        int col = nf*8 + qc*2;
        int r0 = wid*16 + qr, r1 = r0 + 8;
        *(__half2*)(Am + r0*136 + col) = __floats2half2_rn(
            (col <= r0) ? accA[nf][0] : 0.f, (col+1 <= r0) ? accA[nf][1] : 0.f);
        *(__half2*)(Am + r1*136 + col) = __floats2half2_rn(
            (col <= r1) ? accA[nf][2] : 0.f, (col+1 <= r1) ? accA[nf][3] : 0.f);
    }
    __syncthreads();

    for (int kt=0;kt<8;kt++){
        unsigned a[4];
        {
            int row = wid*16 + lrow;
            unsigned ad = sptr((char*)Am + row*272 + kt*32 + lco*16);
            LDM4(a[0],a[1],a[2],a[3],ad);
        }
        int trow = kt*16 + (lane&7) + ((lane&16)>>1);
        unsigned bf[9][2];
        #pragma unroll
        for (int bi=0;bi<4;bi++){
            unsigned ad = sptr(Vt + trow*72 + bi*16 + (lane&8));
            unsigned r0,r1,r2,r3; LDM4T(r0,r1,r2,r3,ad);
            bf[2*bi][0]=r0; bf[2*bi][1]=r2; bf[2*bi+1][0]=r1; bf[2*bi+1][1]=r3;
        }
        {
            unsigned ad = sptr(Vt + (kt*16 + (lane&15))*72 + 64);
            unsigned r0,r1; LDM2T(r0,r1,ad);
            bf[8][0]=r0; bf[8][1]=r1;
        }
        #pragma unroll
        for (int nf=0;nf<9;nf++)
            MMA16(accO[nf], a[0],a[1],a[2],a[3], bf[nf][0], bf[nf][1]);
    }

    float d0 = accO[8][0] + accO[8][1];
    float d1 = accO[8][2] + accO[8][3];
    d0 = __shfl_sync(0xffffffffu, d0, lane & ~3);
    d1 = __shfl_sync(0xffffffffu, d1, lane & ~3);
    float inv0 = 1.f/d0, inv1 = 1.f/d1;

    int b = bh >> 4, h = bh & 15;
    int n0 = c*CHK + wid*16;
    #pragma unroll
    for (int nf=0;nf<8;nf++){
        int col = h*64 + nf*8 + qc*2;
        __half2* o0 = (__half2*)(g_attn + ((size_t)(b*SEQ + n0 + qr))*DM + col);
        __half2* o1 = (__half2*)(g_attn + ((size_t)(b*SEQ + n0 + qr + 8))*DM + col);
        *o0 = __floats2half2_rn(accO[nf][0]*inv0, accO[nf][1]*inv0);
        *o1 = __floats2half2_rn(accO[nf][2]*inv1, accO[nf][3]*inv1);
    }
#undef OCH_ISSUE
}

// ---------------- launch ------------------------------------------------------
extern "C" void kernel_launch(void* const* d_in, const int* in_sizes, int n_in,
                              void* d_out, int out_size)
{
    (void)in_sizes; (void)n_in; (void)out_size;
    const float* x    = (const float*)d_in[0];
    const float* Wq   = (const float*)d_in[1];
    const float* bq   = (const float*)d_in[2];
    const float* Wk   = (const float*)d_in[3];
    const float* bk   = (const float*)d_in[4];
    const float* Wv   = (const float*)d_in[5];
    const float* bv   = (const float*)d_in[6];
    const float* Wo   = (const float*)d_in[7];
    const float* bo   = (const float*)d_in[8];
    const float* proj = (const float*)d_in[9];
    float* out = (float*)d_out;

    cudaFuncSetAttribute(chunk_sums_mma, cudaFuncAttributeMaxDynamicSharedMemorySize, CS_SMEM);
    cudaFuncSetAttribute(out_chunk_h, cudaFuncAttributeMaxDynamicSharedMemorySize, OC_SMEM);
    cudaFuncSetAttribute(hgemm_feat2, cudaFuncAttributeMaxDynamicSharedMemorySize, FQ_SMEM);

    prep_all<<<(N4_ALL+255)/256, 256>>>(x, Wq, Wk, Wv, Wo, proj);

    dim3 gq(3*DM/128, ROWS/128);   // (24, 64)
    hgemm_qkv<<<gq,256>>>(bq, bk, bv);

    dim3 gfeat(TOK/128, 2);
    hgemm_feat2<<<gfeat,256,FQ_SMEM>>>();
    feat_apply_k<<<TOK/8,256>>>();

    chunk_sums_mma<<<BH*NC,256,CS_SMEM>>>();
    dim3 gsc(19, BH);
    scan_par<<<gsc,256>>>();
    out_chunk_h<<<BH*NC,256,OC_SMEM>>>();

    dim3 go(DM/128, ROWS/128);
    hgemm_out<<<go,256>>>(out, bo);
}

// round 13
// speedup vs baseline: 1.0132x; 1.0132x over previous
#include <cuda_runtime.h>
#include <cuda_fp16.h>
#include <math.h>

#define BSZ 2
#define HEADS 16
#define SEQ 4096
#define DH 64
#define DM 1024
#define MF 266
#define MPX 288
#define CHK 128
#define NC 32
#define BH 32
#define TOK (BH*SEQ)
#define ROWS (BSZ*SEQ)

#define NORMALIZER 0.35355339059327373f
#define DIAG_COEF 0.0625f
#define RATIO 0.061313933948496584f
#define KEPS 1e-4f
#define CEPS 1e-6f
#define KSCALE 256.0f
#define LOG2E 1.4426950408889634f
#define LOG2_SCALE_Q (-4.0276427f)
#define LOG2_SCALE_K ( 3.9723573f)
#define KEPS_Q 6.1313934e-6f
#define KEPS_K 1.5696367e-3f

// ---------------- static scratch ----------------
__device__ __half g_qh[(size_t)TOK*DH];
__device__ __half g_kh[(size_t)TOK*DH];
__device__ __half g_vh[(size_t)TOK*DH];
__device__ __half g_qp[(size_t)TOK*MPX];
__device__ __half g_kp[(size_t)TOK*MPX];
__device__ __half g_csh[(size_t)BH*NC*MPX*DH];
__device__ __half g_zsh[(size_t)BH*NC*MPX];
__device__ __half g_attn[(size_t)ROWS*DM];
__device__ __half g_projh[384*DH];
__device__ __half g_xh[(size_t)ROWS*DM];
__device__ __half g_wh3[(size_t)3*DM*DM];
__device__ __half g_who[(size_t)DM*DM];
__device__ unsigned int g_kmax_bits;

__device__ __forceinline__ unsigned int enc_f(float f){
    unsigned int u = __float_as_uint(f);
    return (u & 0x80000000u) ? ~u : (u | 0x80000000u);
}
__device__ __forceinline__ float dec_f(unsigned int u){
    return (u & 0x80000000u) ? __uint_as_float(u & 0x7fffffffu)
                             : __uint_as_float(~u);
}
__device__ __forceinline__ unsigned sptr(const void* p){
    return (unsigned)__cvta_generic_to_shared(p);
}
__device__ __forceinline__ float ex2f(float x){
    float r; asm("ex2.approx.ftz.f32 %0, %1;" : "=f"(r) : "f"(x)); return r;
}
#define CP16(dst,src) asm volatile("cp.async.cg.shared.global [%0], [%1], 16;"::"r"(dst),"l"(src))
#define CPCOMMIT() asm volatile("cp.async.commit_group;")
#define CPWAIT1() asm volatile("cp.async.wait_group 1;")
#define CPWAIT0() asm volatile("cp.async.wait_group 0;")
#define LDM4(r0,r1,r2,r3,addr) \
    asm volatile("ldmatrix.sync.aligned.m8n8.x4.shared.b16 {%0,%1,%2,%3}, [%4];" \
        :"=r"(r0),"=r"(r1),"=r"(r2),"=r"(r3):"r"(addr))
#define LDM2(r0,r1,addr) \
    asm volatile("ldmatrix.sync.aligned.m8n8.x2.shared.b16 {%0,%1}, [%2];" \
        :"=r"(r0),"=r"(r1):"r"(addr))
#define LDM4T(r0,r1,r2,r3,addr) \
    asm volatile("ldmatrix.sync.aligned.m8n8.x4.trans.shared.b16 {%0,%1,%2,%3}, [%4];" \
        :"=r"(r0),"=r"(r1),"=r"(r2),"=r"(r3):"r"(addr))
#define LDM2T(r0,r1,addr) \
    asm volatile("ldmatrix.sync.aligned.m8n8.x2.trans.shared.b16 {%0,%1}, [%2];" \
        :"=r"(r0),"=r"(r1):"r"(addr))
#define MMA16(acc,a0,a1,a2,a3,b0,b1) \
    asm volatile("mma.sync.aligned.m16n8k16.row.col.f32.f16.f16.f32 " \
        "{%0,%1,%2,%3},{%4,%5,%6,%7},{%8,%9},{%0,%1,%2,%3};" \
        :"+f"(acc[0]),"+f"(acc[1]),"+f"(acc[2]),"+f"(acc[3]) \
        :"r"(a0),"r"(a1),"r"(a2),"r"(a3),"r"(b0),"r"(b1))

// ================= fp16 GEMM core =================
#define H_ISSUE(t,Abase,Bbase,Ksz) { int s_=(t)%3; \
    __half* As_=smh+s_*8192; __half* Bs_=As_+4096; \
    const __half* Ag_=(Abase)+(size_t)(t)*32; \
    const __half* Bg_=(Bbase)+(size_t)(t)*32; \
    _Pragma("unroll") for(int h=0;h<2;h++){ \
      int id=tid+h*256; int row=id>>2, cc=id&3; \
      unsigned sw=(unsigned)((cc^((row>>1)&3))*16); \
      CP16(sptr((char*)As_+row*64+sw), Ag_+(size_t)row*(Ksz)+cc*8); \
      CP16(sptr((char*)Bs_+row*64+sw), Bg_+(size_t)row*(Ksz)+cc*8); } \
    CPCOMMIT(); }

#define HGEMM_CORE(Abase,Bbase,Ksz,kt) \
    H_ISSUE(0,Abase,Bbase,Ksz); \
    if ((kt)>1) H_ISSUE(1,Abase,Bbase,Ksz); \
    for (int t=0;t<(kt);t++){ \
        if (t+1<(kt)) CPWAIT1(); else CPWAIT0(); \
        __syncthreads(); \
        __half* As = smh + (t%3)*8192; \
        __half* Bs = As + 4096; \
        _Pragma("unroll") \
        for (int k16=0;k16<2;k16++){ \
            unsigned a[4][4]; \
            _Pragma("unroll") \
            for (int mf=0;mf<4;mf++){ \
                int row = wm + mf*16 + lrow; \
                int qd = 2*k16 + lco; \
                unsigned ad = sptr((char*)As + row*64 + ((qd^((row>>1)&3))*16)); \
                LDM4(a[mf][0],a[mf][1],a[mf][2],a[mf][3],ad); \
            } \
            unsigned b[4][2]; \
            _Pragma("unroll") \
            for (int p=0;p<2;p++){ \
                int row = wn + p*16 + lrow; \
                int qd = 2*k16 + lco; \
                unsigned ad = sptr((char*)Bs + row*64 + ((qd^((row>>1)&3))*16)); \
                unsigned r0,r1,r2,r3; LDM4(r0,r1,r2,r3,ad); \
                b[2*p][0]=r0; b[2*p+1][0]=r1; b[2*p][1]=r2; b[2*p+1][1]=r3; \
            } \
            _Pragma("unroll") \
            for (int mf=0;mf<4;mf++) \
                _Pragma("unroll") \
                for (int nf=0;nf<4;nf++) \
                    MMA16(acc[mf][nf],a[mf][0],a[mf][1],a[mf][2],a[mf][3], \
                          b[nf][0],b[nf][1]); \
        } \
        __syncthreads(); \
        if (t+2<(kt)) H_ISSUE(t+2,Abase,Bbase,Ksz); \
    }

#define GEMM_PREAMBLE() \
    const int tid=threadIdx.x, lane=tid&31, wid=tid>>5; \
    const int wm=(wid&1)*64, wn=(wid>>1)*32; \
    const int qr=lane>>2, qc=lane&3; \
    const int lrow=(lane&7)+(lane&8); \
    const int lco=lane>>4; \
    float acc[4][4][4]; \
    _Pragma("unroll") \
    for(int i=0;i<4;i++) \
        _Pragma("unroll") \
        for(int j=0;j<4;j++){acc[i][j][0]=0;acc[i][j][1]=0;acc[i][j][2]=0;acc[i][j][3]=0;}

// ---------------- fused QKV GEMM ---------------------------------------------
__global__ __launch_bounds__(256,2)
void hgemm_qkv(const float* __restrict__ bq, const float* __restrict__ bk,
               const float* __restrict__ bv)
{
    __shared__ __half smh[3*8192];
    const int m0=blockIdx.y*128, n0=blockIdx.x*128;
    GEMM_PREAMBLE();
    const __half* Abase = g_xh  + (size_t)m0*DM;
    const __half* Bbase = g_wh3 + (size_t)n0*DM;
    HGEMM_CORE(Abase, Bbase, DM, 32);

    #pragma unroll
    for (int mf=0;mf<4;mf++){
        int tr0 = m0 + wm + mf*16 + qr;
        int b0 = tr0 >> 12, n_ = tr0 & 4095;
        #pragma unroll
        for (int nf=0;nf<4;nf++){
            int col = n0 + wn + nf*8 + qc*2;
            int sel = col >> 10;
            int c1  = col & 1023;
            int h = c1 >> 6, d = c1 & 63;
            const float* bias = (sel==0) ? bq : (sel==1) ? bk : bv;
            __half* dst = (sel==0) ? g_qh : (sel==1) ? g_kh : g_vh;
            float bb0 = bias[c1], bb1 = bias[c1+1];
            size_t base0 = (((size_t)(b0*HEADS+h))*SEQ + n_)*DH + d;
            size_t base1 = (((size_t)(b0*HEADS+h))*SEQ + n_ + 8)*DH + d;
            *(__half2*)(dst + base0) = __floats2half2_rn(acc[mf][nf][0]+bb0, acc[mf][nf][1]+bb1);
            *(__half2*)(dst + base1) = __floats2half2_rn(acc[mf][nf][2]+bb0, acc[mf][nf][3]+bb1);
        }
    }
}

// ---------------- output projection GEMM -------------------------------------
__global__ __launch_bounds__(256,2)
void hgemm_out(float* __restrict__ C, const float* __restrict__ bias)
{
    __shared__ __half smh[3*8192];
    const int m0=blockIdx.y*128, n0=blockIdx.x*128;
    GEMM_PREAMBLE();
    const __half* Abase = g_attn + (size_t)m0*DM;
    const __half* Bbase = g_who  + (size_t)n0*DM;
    HGEMM_CORE(Abase, Bbase, DM, 32);

    #pragma unroll
    for (int mf=0;mf<4;mf++){
        #pragma unroll
        for (int nf=0;nf<4;nf++){
            int row = m0 + wm + mf*16 + qr;
            int col = n0 + wn + nf*8 + qc*2;
            float b0 = bias[col], b1 = bias[col+1];
            float2 v0; v0.x=acc[mf][nf][0]+b0; v0.y=acc[mf][nf][1]+b1;
            float2 v1; v1.x=acc[mf][nf][2]+b0; v1.y=acc[mf][nf][3]+b1;
            *(float2*)(C + (size_t)row*DM + col)     = v0;
            *(float2*)(C + (size_t)(row+8)*DM + col) = v1;
        }
    }
}

// ---------------- fused feature GEMM v2: 256 rows/CTA, A double-buffered -----
// halves: Ablk0 @0 (8192 = two 4096 k-slabs), Ablk1 @8192, B0 @16384 (9216),
// B1 @25600 (9216); floats @ half idx 34816: rowmax4[512], diag[128].
#define FB_SMEM (34816*2 + 512*4 + 128*4)
__global__ __launch_bounds__(256,1)
void hgemm_feat2()
{
    extern __shared__ __half sh_dyn[];
    __half* B0 = sh_dyn + 16384;
    __half* B1 = sh_dyn + 25600;
    float* rowmax4 = (float*)(sh_dyn + 34816);
    float* diagb   = rowmax4 + 512;

    const int z = blockIdx.y;               // 0: q (fused), 1: k (raw + max)
    const __half* src = z ? g_kh : g_qh;
    const int tid=threadIdx.x, lane=tid&31, wid=tid>>5;
    const int wm=(wid&1)*64, wn=(wid>>1)*72;
    const int qr=lane>>2, qc=lane&3;
    const int lrow=(lane&7)+(lane&8);
    const int lco=lane>>4;
    const size_t tokbase = (size_t)blockIdx.x*256;

#define FA_ISSUE(b) { __half* A0_=sh_dyn+(b)*8192; __half* A1_=A0_+4096; \
    size_t t0_=tokbase+(size_t)(b)*128; \
    _Pragma("unroll") for (int j=0;j<2;j++){ \
        int cid = tid + j*256; int row = cid>>2, cc = cid&3; \
        unsigned sw = (unsigned)((cc^((row>>1)&3))*16); \
        CP16(sptr((char*)A0_ + row*64 + sw), src + (t0_+row)*DH + cc*8); \
        CP16(sptr((char*)A1_ + row*64 + sw), src + (t0_+row)*DH + 32 + cc*8); } }

    // group0: B + A block0 ; group1: A block1
    #pragma unroll
    for (int j=0;j<5;j++){
        int cid = tid + j*256;
        if (cid < 1152){
            int row = cid>>2, cc = cid&3;
            unsigned sw = (unsigned)((cc^((row>>1)&3))*16);
            CP16(sptr((char*)B0 + row*64 + sw), g_projh + row*DH + cc*8);
            CP16(sptr((char*)B1 + row*64 + sw), g_projh + row*DH + 32 + cc*8);
        }
    }
    FA_ISSUE(0); CPCOMMIT();
    FA_ISSUE(1); CPCOMMIT();
    CPWAIT1();
    __syncthreads();

    float mxk = -3.4e38f;   // k-side running block max

    for (int b=0; b<2; b++){
        if (b==1){ CPWAIT0(); __syncthreads(); }
        __half* A0 = sh_dyn + b*8192;
        __half* A1 = A0 + 4096;
        const size_t tok0 = tokbase + (size_t)b*128;

        if (z==0 && tid < 128){
            float s = 0.f;
            #pragma unroll
            for (int st=0; st<2; st++){
                const char* Ab = (const char*)(st ? A1 : A0);
                #pragma unroll
                for (int cc=0;cc<4;cc++){
                    uint4 u = *(const uint4*)(Ab + tid*64 + ((cc^((tid>>1)&3))*16));
                    const __half2* hp = (const __half2*)&u;
                    #pragma unroll
                    for (int p=0;p<4;p++){
                        float2 f = __half22float2(hp[p]);
                        s = fmaf(f.x,f.x,s); s = fmaf(f.y,f.y,s);
                    }
                }
            }
            diagb[tid] = DIAG_COEF * s;
        }

        float acc[4][9][4];
        #pragma unroll
        for (int i=0;i<4;i++)
            #pragma unroll
            for (int j=0;j<9;j++){acc[i][j][0]=0;acc[i][j][1]=0;acc[i][j][2]=0;acc[i][j][3]=0;}

        #pragma unroll
        for (int k16=0;k16<4;k16++){
            __half* As = (k16<2) ? A0 : A1;
            __half* Bs = (k16<2) ? B0 : B1;
            int kk = k16 & 1;
            unsigned a[4][4];
            #pragma unroll
            for (int mf=0;mf<4;mf++){
                int row = wm + mf*16 + lrow;
                int qd = 2*kk + lco;
                unsigned ad = sptr((char*)As + row*64 + ((qd^((row>>1)&3))*16));
                LDM4(a[mf][0],a[mf][1],a[mf][2],a[mf][3],ad);
            }
            unsigned bfr[9][2];
            #pragma unroll
            for (int p=0;p<4;p++){
                int row = wn + p*16 + lrow;
                int qd = 2*kk + lco;
                unsigned ad = sptr((char*)Bs + row*64 + ((qd^((row>>1)&3))*16));
                unsigned r0,r1,r2,r3; LDM4(r0,r1,r2,r3,ad);
                bfr[2*p][0]=r0; bfr[2*p+1][0]=r1; bfr[2*p][1]=r2; bfr[2*p+1][1]=r3;
            }
            {
                int row8 = wn + 64 + (lane&7);
                int ch = 2*kk + ((lane>>3)&1);
                unsigned ad = sptr((char*)Bs + row8*64 + ((ch^((row8>>1)&3))*16));
                unsigned r0,r1; LDM2(r0,r1,ad);
                bfr[8][0]=r0; bfr[8][1]=r1;
            }
            #pragma unroll
            for (int mf=0;mf<4;mf++)
                #pragma unroll
                for (int nf=0;nf<9;nf++)
                    MMA16(acc[mf][nf], a[mf][0],a[mf][1],a[mf][2],a[mf][3],
                          bfr[nf][0], bfr[nf][1]);
        }

        if (z){
            #pragma unroll
            for (int mf=0;mf<4;mf++){
                #pragma unroll
                for (int h=0;h<2;h++){
                    int row = wm + mf*16 + qr + 8*h;
                    #pragma unroll
                    for (int nf=0;nf<9;nf++){
                        int col = wn + nf*8 + qc*2;
                        float v0 = acc[mf][nf][2*h], v1 = acc[mf][nf][2*h+1];
                        *(__half2*)(g_kp + (tok0+row)*MPX + col) = __floats2half2_rn(v0, v1);
                        if (col   < MF) mxk = fmaxf(mxk, v0);
                        if (col+1 < MF) mxk = fmaxf(mxk, v1);
                    }
                }
            }
            __syncthreads();   // (uniform) protect smem reuse across blocks
            continue;
        }

        // q side: rowmax + exp + store
        float pm[4][2];
        #pragma unroll
        for (int mf=0;mf<4;mf++){ pm[mf][0]=-3.4e38f; pm[mf][1]=-3.4e38f; }
        #pragma unroll
        for (int mf=0;mf<4;mf++)
            #pragma unroll
            for (int nf=0;nf<9;nf++){
                int col = wn + nf*8 + qc*2;
                if (col < MF){
                    pm[mf][0] = fmaxf(pm[mf][0], acc[mf][nf][0]);
                    pm[mf][1] = fmaxf(pm[mf][1], acc[mf][nf][2]);
                }
                if (col+1 < MF){
                    pm[mf][0] = fmaxf(pm[mf][0], acc[mf][nf][1]);
                    pm[mf][1] = fmaxf(pm[mf][1], acc[mf][nf][3]);
                }
            }
        #pragma unroll
        for (int o=1;o<4;o<<=1)
            #pragma unroll
            for (int mf=0;mf<4;mf++){
                pm[mf][0] = fmaxf(pm[mf][0], __shfl_xor_sync(0xffffffffu, pm[mf][0], o));
                pm[mf][1] = fmaxf(pm[mf][1], __shfl_xor_sync(0xffffffffu, pm[mf][1], o));
            }
        if (qc==0){
            #pragma unroll
            for (int mf=0;mf<4;mf++){
                rowmax4[(wm+mf*16+qr  )*4 + (wid>>1)] = pm[mf][0];
                rowmax4[(wm+mf*16+qr+8)*4 + (wid>>1)] = pm[mf][1];
            }
        }
        __syncthreads();

        #pragma unroll
        for (int mf=0;mf<4;mf++){
            #pragma unroll
            for (int h=0;h<2;h++){
                int row = wm + mf*16 + qr + 8*h;
                const float* rm = rowmax4 + row*4;
                float mx = fmaxf(fmaxf(rm[0],rm[1]), fmaxf(rm[2],rm[3]));
                float base = fmaf(-(diagb[row]+mx), LOG2E, LOG2_SCALE_Q);
                #pragma unroll
                for (int nf=0;nf<9;nf++){
                    int col = wn + nf*8 + qc*2;
                    float w0 = (col   < MF) ? (ex2f(fmaf(acc[mf][nf][2*h  ], LOG2E, base)) + KEPS_Q) : 0.f;
                    float w1 = (col+1 < MF) ? (ex2f(fmaf(acc[mf][nf][2*h+1], LOG2E, base)) + KEPS_Q) : 0.f;
                    *(__half2*)(g_qp + (tok0+row)*MPX + col) = __floats2half2_rn(w0, w1);
                }
            }
        }
        __syncthreads();   // protect rowmax4/diagb reuse for next block
    }

    if (z){
        #pragma unroll
        for (int o=16;o;o>>=1) mxk = fmaxf(mxk, __shfl_xor_sync(0xffffffffu, mxk, o));
        if (lane==0) rowmax4[wid] = mxk;
        __syncthreads();
        if (tid==0){
            float m = rowmax4[0];
            #pragma unroll
            for (int w=1;w<8;w++) m = fmaxf(m, rowmax4[w]);
            atomicMax(&g_kmax_bits, enc_f(m));
        }
    }
#undef FA_ISSUE
}

// ---------------- fused prep ----------------
#define N4_X (ROWS*DM/4)
#define N4_W (DM*DM/4)
#define N4_P (384*DH/4)
#define N4_ALL (N4_X + 4*N4_W + N4_P)
__global__ void prep_all(const float* __restrict__ x,  const float* __restrict__ Wq,
                         const float* __restrict__ Wk, const float* __restrict__ Wv,
                         const float* __restrict__ Wo, const float* __restrict__ proj)
{
    long i = (long)blockIdx.x*256 + threadIdx.x;
    if (i == 0) g_kmax_bits = 0u;
    if (i < N4_X){
        float4 v = ((const float4*)x)[i];
        ((__half2*)g_xh)[i*2]   = __floats2half2_rn(v.x, v.y);
        ((__half2*)g_xh)[i*2+1] = __floats2half2_rn(v.z, v.w);
        return;
    }
    i -= N4_X;
    if (i < 4L*N4_W){
        int w = (int)(i / N4_W); long j = i % N4_W;
        const float* src = (w==0)?Wq:(w==1)?Wk:(w==2)?Wv:Wo;
        __half* dst = (w<3) ? (g_wh3 + (size_t)w*DM*DM) : g_who;
        float4 v = ((const float4*)src)[j];
        ((__half2*)dst)[j*2]   = __floats2half2_rn(v.x, v.y);
        ((__half2*)dst)[j*2+1] = __floats2half2_rn(v.z, v.w);
        return;
    }
    i -= 4L*N4_W;
    if (i < N4_P){
        long e = i*4;
        #pragma unroll
        for (int j=0;j<4;j++){
            long m = (e+j)/DH, d = (e+j)%DH;
            g_projh[e+j] = (m < MF) ? __float2half(proj[m*DH+d]*NORMALIZER)
                                    : __float2half(0.f);
        }
    }
}

// ---------------- exp feature map for k (global max) -------------------------
__device__ __forceinline__ void unpack8(uint4 c, float* v){
    float2 t;
    t=__half22float2(*(__half2*)&c.x); v[0]=t.x; v[1]=t.y;
    t=__half22float2(*(__half2*)&c.y); v[2]=t.x; v[3]=t.y;
    t=__half22float2(*(__half2*)&c.z); v[4]=t.x; v[5]=t.y;
    t=__half22float2(*(__half2*)&c.w); v[6]=t.x; v[7]=t.y;
}
__device__ __forceinline__ uint4 pack8(const float* v){
    uint4 c;
    *(__half2*)&c.x = __floats2half2_rn(v[0],v[1]);
    *(__half2*)&c.y = __floats2half2_rn(v[2],v[3]);
    *(__half2*)&c.z = __floats2half2_rn(v[4],v[5]);
    *(__half2*)&c.w = __floats2half2_rn(v[6],v[7]);
    return c;
}
__global__ void feat_apply_k()
{
    int warp = threadIdx.x >> 5, lane = threadIdx.x & 31;
    size_t row = (size_t)blockIdx.x*8 + warp;
    float2 qq = __half22float2(((const __half2*)(g_kh + row*DH))[lane]);
    float s = qq.x*qq.x + qq.y*qq.y;
    #pragma unroll
    for (int o=16;o;o>>=1) s += __shfl_xor_sync(0xffffffffu, s, o);
    float diag = DIAG_COEF * s;

    __half* dd = g_kp + row*MPX;
    uint4 c0 = ((const uint4*)dd)[lane];
    uint4 c1 = make_uint4(0,0,0,0);
    bool act1 = lane < 4;
    if (act1) c1 = ((const uint4*)dd)[32 + lane];
    float v0[8], v1[8];
    unpack8(c0, v0); unpack8(c1, v1);

    float mx = dec_f(g_kmax_bits);
    const float base = fmaf(-(diag+mx), LOG2E, LOG2_SCALE_K);
    float w0[8], w1[8];
    #pragma unroll
    for (int j=0;j<8;j++) w0[j] = ex2f(fmaf(v0[j], LOG2E, base)) + KEPS_K;
    #pragma unroll
    for (int j=0;j<8;j++){
        int m = 256 + lane*8 + j;
        w1[j] = (m < MF) ? (ex2f(fmaf(v1[j], LOG2E, base)) + KEPS_K) : 0.f;
    }
    ((uint4*)dd)[lane] = pack8(w0);
    if (act1) ((uint4*)dd)[32 + lane] = pack8(w1);
}

// ---------------- chunk sums via fp16 MMA ------------------------------------
#define CS_SMEM ((128*296 + 128*72)*2)
extern __shared__ __half sh_dyn2[];
__global__ __launch_bounds__(256)
void chunk_sums_mma()
{
    __half* Kt = sh_dyn2;
    __half* Vt = sh_dyn2 + 128*296;
    const int tid=threadIdx.x, lane=tid&31, wid=tid>>5;
    const int blk=blockIdx.x;
    const size_t tok0=(size_t)blk*CHK;
    const int qr=lane>>2, qc=lane&3;

    #pragma unroll
    for (int j=0;j<18;j++){
        int cid = tid + j*256; int row = cid/36, c = cid%36;
        CP16(sptr(Kt + row*296 + c*8), g_kp + (tok0+row)*MPX + c*8);
    }
    #pragma unroll
    for (int j=0;j<4;j++){
        int cid = tid + j*256; int row = cid>>3, c = cid&7;
        CP16(sptr(Vt + row*72 + c*8), g_vh + (tok0+row)*DH + c*8);
    }
    CPCOMMIT(); CPWAIT0();
    __syncthreads();
    if (tid < 128){
        __half* vr = Vt + tid*72;
        vr[64] = __float2half(1.f);
        #pragma unroll
        for (int j=65;j<72;j++) vr[j] = __float2half(0.f);
    }
    __syncthreads();

    const int nfr = (wid<2) ? 3 : 2;
    int mfs[3]; mfs[0]=wid; mfs[1]=wid+8; mfs[2]=16+wid;
    float acc[3][9][4];
    #pragma unroll
    for(int i=0;i<3;i++)
        #pragma unroll
        for(int j=0;j<9;j++){acc[i][j][0]=0;acc[i][j][1]=0;acc[i][j][2]=0;acc[i][j][3]=0;}

    for (int ks=0;ks<8;ks++){
        int k0 = ks*16;
        int trow = k0 + (lane&7) + ((lane&16)>>1);
        unsigned bf[9][2];
        #pragma unroll
        for (int bi=0;bi<4;bi++){
            unsigned ad = sptr(Vt + trow*72 + bi*16 + (lane&8));
            unsigned r0,r1,r2,r3; LDM4T(r0,r1,r2,r3,ad);
            bf[2*bi][0]=r0; bf[2*bi][1]=r2; bf[2*bi+1][0]=r1; bf[2*bi+1][1]=r3;
        }
        {
            unsigned ad = sptr(Vt + (k0 + (lane&15))*72 + 64);
            unsigned r0,r1; LDM2T(r0,r1,ad);
            bf[8][0]=r0; bf[8][1]=r1;
        }
        for (int fi=0; fi<nfr; fi++){
            unsigned ad = sptr(Kt + trow*296 + mfs[fi]*16 + (lane&8));
            unsigned a0,a1,a2,a3; LDM4T(a0,a1,a2,a3,ad);
            #pragma unroll
            for (int nf=0;nf<9;nf++)
                MMA16(acc[fi][nf], a0,a1,a2,a3, bf[nf][0], bf[nf][1]);
        }
    }

    for (int fi=0; fi<nfr; fi++){
        int m0 = mfs[fi]*16;
        #pragma unroll
        for (int nf=0;nf<8;nf++){
            int col = nf*8 + qc*2;
            *(__half2*)(g_csh + ((size_t)blk*MPX + m0+qr)*DH + col)   = __floats2half2_rn(acc[fi][nf][0], acc[fi][nf][1]);
            *(__half2*)(g_csh + ((size_t)blk*MPX + m0+qr+8)*DH + col) = __floats2half2_rn(acc[fi][nf][2], acc[fi][nf][3]);
        }
        if (qc==0){
            g_zsh[(size_t)blk*MPX + m0+qr]   = __float2half(acc[fi][8][0]);
            g_zsh[(size_t)blk*MPX + m0+qr+8] = __float2half(acc[fi][8][2]);
        }
    }
}

// ---------------- parallel exclusive scan (uint2 + prefetch) -----------------
__global__ __launch_bounds__(256)
void scan_par()
{
    int bh = blockIdx.y;
    if (blockIdx.x < 18){
        int l = blockIdx.x*256 + threadIdx.x;
        uint2* base = (uint2*)(g_csh + (size_t)bh*NC*MPX*DH) + l;
        const int stride = MPX*DH/4;
        float s0=0.f,s1=0.f,s2=0.f,s3=0.f;
        uint2 cur = base[0];
        #pragma unroll
        for (int c=0;c<NC;c++){
            uint2 nxt = make_uint2(0,0);
            if (c+1<NC) nxt = base[(size_t)(c+1)*stride];
            float2 t0 = __half22float2(*(__half2*)&cur.x);
            float2 t1 = __half22float2(*(__half2*)&cur.y);
            uint2 o;
            *(__half2*)&o.x = __floats2half2_rn(s0, s1);
            *(__half2*)&o.y = __floats2half2_rn(s2, s3);
            base[(size_t)c*stride] = o;
            s0 += t0.x; s1 += t0.y; s2 += t1.x; s3 += t1.y;
            cur = nxt;
        }
    } else {
        if (threadIdx.x < 72){
            uint2* base = (uint2*)(g_zsh + (size_t)bh*NC*MPX) + threadIdx.x;
            const int stride = MPX/4;
            float s0=0.f,s1=0.f,s2=0.f,s3=0.f;
            uint2 cur = base[0];
            #pragma unroll
            for (int c=0;c<NC;c++){
                uint2 nxt = make_uint2(0,0);
                if (c+1<NC) nxt = base[(size_t)(c+1)*stride];
                float2 t0 = __half22float2(*(__half2*)&cur.x);
                float2 t1 = __half22float2(*(__half2*)&cur.y);
                uint2 o;
                *(__half2*)&o.x = __floats2half2_rn(s0, s1);
                *(__half2*)&o.y = __floats2half2_rn(s2, s3);
                base[(size_t)c*stride] = o;
                s0 += t0.x; s1 += t0.y; s2 += t1.x; s3 += t1.y;
                cur = nxt;
            }
        }
    }
}

// ---------------- out_chunk via fp16 MMA --------------------------------------
#define OC_STAGE 10496
#define OC_VT 20992
#define OC_SMEM ((20992 + 128*72)*2)
__global__ __launch_bounds__(256)
void out_chunk_h()
{
    __half* Am = sh_dyn2;
    __half* Vt = sh_dyn2 + OC_VT;
    const int tid=threadIdx.x, lane=tid&31, wid=tid>>5;
    const int blk=blockIdx.x, bh=blk>>5, c=blk&31;
    const size_t tok0=(size_t)blk*CHK;
    const int qr=lane>>2, qc=lane&3;
    const int lrow=(lane&7)+(lane&8);
    const int lco=lane>>4;
    const __half ceps_h = __float2half(KSCALE*CEPS);

    #pragma unroll
    for (int j=0;j<4;j++){
        int cid = tid + j*256; int row = cid>>3, cc = cid&7;
        CP16(sptr(Vt + row*72 + cc*8), g_vh + (tok0+row)*DH + cc*8);
    }

    float accA[16][4];
    float accO[9][4];
    #pragma unroll
    for(int i=0;i<16;i++){accA[i][0]=0;accA[i][1]=0;accA[i][2]=0;accA[i][3]=0;}
    #pragma unroll
    for(int i=0;i<9;i++){accO[i][0]=0;accO[i][1]=0;accO[i][2]=0;accO[i][3]=0;}

#define OCH_ISSUE(t) { int s_=(t)&1; \
    __half* Qs_=sh_dyn2+s_*OC_STAGE; __half* Ks_=Qs_+4096; __half* Ss_=Qs_+8192; \
    _Pragma("unroll") for(int h=0;h<2;h++){ \
      int id=tid+h*256; int row=id>>2, cc=id&3; \
      unsigned sw=(unsigned)((cc^((row>>1)&3))*16); \
      CP16(sptr((char*)Qs_+row*64+sw), g_qp+(tok0+row)*MPX+(t)*32+cc*8); \
      CP16(sptr((char*)Ks_+row*64+sw), g_kp+(tok0+row)*MPX+(t)*32+cc*8); } \
    { int row=tid>>3, cc=tid&7; \
      CP16(sptr(Ss_+row*72+cc*8), g_csh+((size_t)blk*MPX+(t)*32+row)*DH+cc*8); } \
    if (tid<32){ __half* sr=Ss_+tid*72; sr[64]=g_zsh[(size_t)blk*MPX+(t)*32+tid]; \
      sr[65]=ceps_h; \
      _Pragma("unroll") for(int j=66;j<72;j++) sr[j]=__float2half(0.f); } \
    CPCOMMIT(); }

    OCH_ISSUE(0);
    for (int t=0;t<9;t++){
        if (t+1<9) OCH_ISSUE(t+1);
        if (t<8) CPWAIT1(); else CPWAIT0();
        __syncthreads();
        __half* Qs = sh_dyn2 + (t&1)*OC_STAGE;
        __half* Ks = Qs + 4096;
        __half* Ss = Qs + 8192;
        #pragma unroll
        for (int k16=0;k16<2;k16++){
            unsigned a[4];
            {
                int row = wid*16 + lrow;
                int qd = 2*k16 + lco;
                unsigned ad = sptr((char*)Qs + row*64 + ((qd^((row>>1)&3))*16));
                LDM4(a[0],a[1],a[2],a[3],ad);
            }
            #pragma unroll
            for (int p=0;p<8;p++){
                int row = p*16 + lrow;
                int qd = 2*k16 + lco;
                unsigned ad = sptr((char*)Ks + row*64 + ((qd^((row>>1)&3))*16));
                unsigned r0,r1,r2,r3; LDM4(r0,r1,r2,r3,ad);
                MMA16(accA[2*p],  a[0],a[1],a[2],a[3], r0, r2);
                MMA16(accA[2*p+1],a[0],a[1],a[2],a[3], r1, r3);
            }
            {
                int trow = k16*16 + (lane&7) + ((lane&16)>>1);
                unsigned bf[9][2];
                #pragma unroll
                for (int bi=0;bi<4;bi++){
                    unsigned ad = sptr(Ss + trow*72 + bi*16 + (lane&8));
                    unsigned r0,r1,r2,r3; LDM4T(r0,r1,r2,r3,ad);
                    bf[2*bi][0]=r0; bf[2*bi][1]=r2; bf[2*bi+1][0]=r1; bf[2*bi+1][1]=r3;
                }
                {
                    unsigned ad = sptr(Ss + (k16*16 + (lane&15))*72 + 64);
                    unsigned r0,r1; LDM2T(r0,r1,ad);
                    bf[8][0]=r0; bf[8][1]=r1;
                }
                #pragma unroll
                for (int nf=0;nf<9;nf++)
                    MMA16(accO[nf], a[0],a[1],a[2],a[3], bf[nf][0], bf[nf][1]);
            }
        }
        __syncthreads();
    }

    if (tid < 128){
        __half* vr = Vt + tid*72;
        vr[64] = __float2half(1.f);
        #pragma unroll
        for (int j=65;j<72;j++) vr[j] = __float2half(0.f);
    }
    #pragma unroll
    for (int nf=0;nf<16;nf++){
        int col = nf*8 + qc*2;
        int r0 = wid*16 + qr, r1 = r0 + 8;
        *(__half2*)(Am + r0*136 + col) = __floats2half2_rn(
            (col <= r0) ? accA[nf][0] : 0.f, (col+1 <= r0) ? accA[nf][1] : 0.f);
        *(__half2*)(Am + r1*136 + col) = __floats2half2_rn(
            (col <= r1) ? accA[nf][2] : 0.f, (col+1 <= r1) ? accA[nf][3] : 0.f);
    }
    __syncthreads();

    for (int kt=0;kt<8;kt++){
        unsigned a[4];
        {
            int row = wid*16 + lrow;
            unsigned ad = sptr((char*)Am + row*272 + kt*32 + lco*16);
            LDM4(a[0],a[1],a[2],a[3],ad);
        }
        int trow = kt*16 + (lane&7) + ((lane&16)>>1);
        unsigned bf[9][2];
        #pragma unroll
        for (int bi=0;bi<4;bi++){
            unsigned ad = sptr(Vt + trow*72 + bi*16 + (lane&8));
            unsigned r0,r1,r2,r3; LDM4T(r0,r1,r2,r3,ad);
            bf[2*bi][0]=r0; bf[2*bi][1]=r2; bf[2*bi+1][0]=r1; bf[2*bi+1][1]=r3;
        }
        {
            unsigned ad = sptr(Vt + (kt*16 + (lane&15))*72 + 64);
            unsigned r0,r1; LDM2T(r0,r1,ad);
            bf[8][0]=r0; bf[8][1]=r1;
        }
        #pragma unroll
        for (int nf=0;nf<9;nf++)
            MMA16(accO[nf], a[0],a[1],a[2],a[3], bf[nf][0], bf[nf][1]);
    }

    float d0 = accO[8][0] + accO[8][1];
    float d1 = accO[8][2] + accO[8][3];
    d0 = __shfl_sync(0xffffffffu, d0, lane & ~3);
    d1 = __shfl_sync(0xffffffffu, d1, lane & ~3);
    float inv0 = 1.f/d0, inv1 = 1.f/d1;

    int b = bh >> 4, h = bh & 15;
    int n0 = c*CHK + wid*16;
    #pragma unroll
    for (int nf=0;nf<8;nf++){
        int col = h*64 + nf*8 + qc*2;
        __half2* o0 = (__half2*)(g_attn + ((size_t)(b*SEQ + n0 + qr))*DM + col);
        __half2* o1 = (__half2*)(g_attn + ((size_t)(b*SEQ + n0 + qr + 8))*DM + col);
        *o0 = __floats2half2_rn(accO[nf][0]*inv0, accO[nf][1]*inv0);
        *o1 = __floats2half2_rn(accO[nf][2]*inv1, accO[nf][3]*inv1);
    }
#undef OCH_ISSUE
}

// ---------------- launch ------------------------------------------------------
extern "C" void kernel_launch(void* const* d_in, const int* in_sizes, int n_in,
                              void* d_out, int out_size)
{
    (void)in_sizes; (void)n_in; (void)out_size;
    const float* x    = (const float*)d_in[0];
    const float* Wq   = (const float*)d_in[1];
    const float* bq   = (const float*)d_in[2];
    const float* Wk   = (const float*)d_in[3];
    const float* bk   = (const float*)d_in[4];
    const float* Wv   = (const float*)d_in[5];
    const float* bv   = (const float*)d_in[6];
    const float* Wo   = (const float*)d_in[7];
    const float* bo   = (const float*)d_in[8];
    const float* proj = (const float*)d_in[9];
    float* out = (float*)d_out;

    cudaFuncSetAttribute(chunk_sums_mma, cudaFuncAttributeMaxDynamicSharedMemorySize, CS_SMEM);
    cudaFuncSetAttribute(out_chunk_h, cudaFuncAttributeMaxDynamicSharedMemorySize, OC_SMEM);
    cudaFuncSetAttribute(hgemm_feat2, cudaFuncAttributeMaxDynamicSharedMemorySize, FB_SMEM);

    prep_all<<<(N4_ALL+255)/256, 256>>>(x, Wq, Wk, Wv, Wo, proj);

    dim3 gq(3*DM/128, ROWS/128);   // (24, 64)
    hgemm_qkv<<<gq,256>>>(bq, bk, bv);

    dim3 gfeat(TOK/256, 2);
    hgemm_feat2<<<gfeat,256,FB_SMEM>>>();
    feat_apply_k<<<TOK/8,256>>>();

    chunk_sums_mma<<<BH*NC,256,CS_SMEM>>>();
    dim3 gsc(19, BH);
    scan_par<<<gsc,256>>>();
    out_chunk_h<<<BH*NC,256,OC_SMEM>>>();

    dim3 go(DM/128, ROWS/128);
    hgemm_out<<<go,256>>>(out, bo);
}

// round 14
// speedup vs baseline: 1.0145x; 1.0013x over previous
#include <cuda_runtime.h>
#include <cuda_fp16.h>
#include <math.h>

#define BSZ 2
#define HEADS 16
#define SEQ 4096
#define DH 64
#define DM 1024
#define MF 266
#define MPX 288
#define CHK 128
#define NC 32
#define BH 32
#define TOK (BH*SEQ)
#define ROWS (BSZ*SEQ)

#define NORMALIZER 0.35355339059327373f
#define DIAG_COEF 0.0625f
#define RATIO 0.061313933948496584f
#define KEPS 1e-4f
#define CEPS 1e-6f
#define KSCALE 256.0f
#define LOG2E 1.4426950408889634f
#define LOG2_SCALE_Q (-4.0276427f)
#define LOG2_SCALE_K ( 3.9723573f)
#define KEPS_Q 6.1313934e-6f
#define KEPS_K 1.5696367e-3f

// ---------------- static scratch ----------------
__device__ __half g_qh[(size_t)TOK*DH];
__device__ __half g_kh[(size_t)TOK*DH];
__device__ __half g_vh[(size_t)TOK*DH];
__device__ __half g_qp[(size_t)TOK*MPX];
__device__ __half g_kp[(size_t)TOK*MPX];
__device__ __half g_csh[(size_t)BH*NC*MPX*DH];
__device__ __half g_zsh[(size_t)BH*NC*MPX];
__device__ __half g_attn[(size_t)ROWS*DM];
__device__ __half g_projh[384*DH];
__device__ __half g_xh[(size_t)ROWS*DM];
__device__ __half g_wh3[(size_t)3*DM*DM];
__device__ __half g_who[(size_t)DM*DM];
__device__ float  g_diagk[(size_t)TOK];
__device__ unsigned int g_kmax_bits;

__device__ __forceinline__ unsigned int enc_f(float f){
    unsigned int u = __float_as_uint(f);
    return (u & 0x80000000u) ? ~u : (u | 0x80000000u);
}
__device__ __forceinline__ float dec_f(unsigned int u){
    return (u & 0x80000000u) ? __uint_as_float(u & 0x7fffffffu)
                             : __uint_as_float(~u);
}
__device__ __forceinline__ unsigned sptr(const void* p){
    return (unsigned)__cvta_generic_to_shared(p);
}
__device__ __forceinline__ float ex2f(float x){
    float r; asm("ex2.approx.ftz.f32 %0, %1;" : "=f"(r) : "f"(x)); return r;
}
__device__ __forceinline__ void unpack8(uint4 c, float* v){
    float2 t;
    t=__half22float2(*(__half2*)&c.x); v[0]=t.x; v[1]=t.y;
    t=__half22float2(*(__half2*)&c.y); v[2]=t.x; v[3]=t.y;
    t=__half22float2(*(__half2*)&c.z); v[4]=t.x; v[5]=t.y;
    t=__half22float2(*(__half2*)&c.w); v[6]=t.x; v[7]=t.y;
}
__device__ __forceinline__ uint4 pack8(const float* v){
    uint4 c;
    *(__half2*)&c.x = __floats2half2_rn(v[0],v[1]);
    *(__half2*)&c.y = __floats2half2_rn(v[2],v[3]);
    *(__half2*)&c.z = __floats2half2_rn(v[4],v[5]);
    *(__half2*)&c.w = __floats2half2_rn(v[6],v[7]);
    return c;
}
#define CP16(dst,src) asm volatile("cp.async.cg.shared.global [%0], [%1], 16;"::"r"(dst),"l"(src))
#define CPCOMMIT() asm volatile("cp.async.commit_group;")
#define CPWAIT1() asm volatile("cp.async.wait_group 1;")
#define CPWAIT0() asm volatile("cp.async.wait_group 0;")
#define LDM4(r0,r1,r2,r3,addr) \
    asm volatile("ldmatrix.sync.aligned.m8n8.x4.shared.b16 {%0,%1,%2,%3}, [%4];" \
        :"=r"(r0),"=r"(r1),"=r"(r2),"=r"(r3):"r"(addr))
#define LDM2(r0,r1,addr) \
    asm volatile("ldmatrix.sync.aligned.m8n8.x2.shared.b16 {%0,%1}, [%2];" \
        :"=r"(r0),"=r"(r1):"r"(addr))
#define LDM4T(r0,r1,r2,r3,addr) \
    asm volatile("ldmatrix.sync.aligned.m8n8.x4.trans.shared.b16 {%0,%1,%2,%3}, [%4];" \
        :"=r"(r0),"=r"(r1),"=r"(r2),"=r"(r3):"r"(addr))
#define LDM2T(r0,r1,addr) \
    asm volatile("ldmatrix.sync.aligned.m8n8.x2.trans.shared.b16 {%0,%1}, [%2];" \
        :"=r"(r0),"=r"(r1):"r"(addr))
#define MMA16(acc,a0,a1,a2,a3,b0,b1) \
    asm volatile("mma.sync.aligned.m16n8k16.row.col.f32.f16.f16.f32 " \
        "{%0,%1,%2,%3},{%4,%5,%6,%7},{%8,%9},{%0,%1,%2,%3};" \
        :"+f"(acc[0]),"+f"(acc[1]),"+f"(acc[2]),"+f"(acc[3]) \
        :"r"(a0),"r"(a1),"r"(a2),"r"(a3),"r"(b0),"r"(b1))

// ================= fp16 GEMM core =================
#define H_ISSUE(t,Abase,Bbase,Ksz) { int s_=(t)%3; \
    __half* As_=smh+s_*8192; __half* Bs_=As_+4096; \
    const __half* Ag_=(Abase)+(size_t)(t)*32; \
    const __half* Bg_=(Bbase)+(size_t)(t)*32; \
    _Pragma("unroll") for(int h=0;h<2;h++){ \
      int id=tid+h*256; int row=id>>2, cc=id&3; \
      unsigned sw=(unsigned)((cc^((row>>1)&3))*16); \
      CP16(sptr((char*)As_+row*64+sw), Ag_+(size_t)row*(Ksz)+cc*8); \
      CP16(sptr((char*)Bs_+row*64+sw), Bg_+(size_t)row*(Ksz)+cc*8); } \
    CPCOMMIT(); }

#define HGEMM_CORE(Abase,Bbase,Ksz,kt) \
    H_ISSUE(0,Abase,Bbase,Ksz); \
    if ((kt)>1) H_ISSUE(1,Abase,Bbase,Ksz); \
    for (int t=0;t<(kt);t++){ \
        if (t+1<(kt)) CPWAIT1(); else CPWAIT0(); \
        __syncthreads(); \
        __half* As = smh + (t%3)*8192; \
        __half* Bs = As + 4096; \
        _Pragma("unroll") \
        for (int k16=0;k16<2;k16++){ \
            unsigned a[4][4]; \
            _Pragma("unroll") \
            for (int mf=0;mf<4;mf++){ \
                int row = wm + mf*16 + lrow; \
                int qd = 2*k16 + lco; \
                unsigned ad = sptr((char*)As + row*64 + ((qd^((row>>1)&3))*16)); \
                LDM4(a[mf][0],a[mf][1],a[mf][2],a[mf][3],ad); \
            } \
            unsigned b[4][2]; \
            _Pragma("unroll") \
            for (int p=0;p<2;p++){ \
                int row = wn + p*16 + lrow; \
                int qd = 2*k16 + lco; \
                unsigned ad = sptr((char*)Bs + row*64 + ((qd^((row>>1)&3))*16)); \
                unsigned r0,r1,r2,r3; LDM4(r0,r1,r2,r3,ad); \
                b[2*p][0]=r0; b[2*p+1][0]=r1; b[2*p][1]=r2; b[2*p+1][1]=r3; \
            } \
            _Pragma("unroll") \
            for (int mf=0;mf<4;mf++) \
                _Pragma("unroll") \
                for (int nf=0;nf<4;nf++) \
                    MMA16(acc[mf][nf],a[mf][0],a[mf][1],a[mf][2],a[mf][3], \
                          b[nf][0],b[nf][1]); \
        } \
        __syncthreads(); \
        if (t+2<(kt)) H_ISSUE(t+2,Abase,Bbase,Ksz); \
    }

#define GEMM_PREAMBLE() \
    const int tid=threadIdx.x, lane=tid&31, wid=tid>>5; \
    const int wm=(wid&1)*64, wn=(wid>>1)*32; \
    const int qr=lane>>2, qc=lane&3; \
    const int lrow=(lane&7)+(lane&8); \
    const int lco=lane>>4; \
    float acc[4][4][4]; \
    _Pragma("unroll") \
    for(int i=0;i<4;i++) \
        _Pragma("unroll") \
        for(int j=0;j<4;j++){acc[i][j][0]=0;acc[i][j][1]=0;acc[i][j][2]=0;acc[i][j][3]=0;}

// ---------------- fused QKV GEMM ---------------------------------------------
__global__ __launch_bounds__(256,2)
void hgemm_qkv(const float* __restrict__ bq, const float* __restrict__ bk,
               const float* __restrict__ bv)
{
    __shared__ __half smh[3*8192];
    const int m0=blockIdx.y*128, n0=blockIdx.x*128;
    GEMM_PREAMBLE();
    const __half* Abase = g_xh  + (size_t)m0*DM;
    const __half* Bbase = g_wh3 + (size_t)n0*DM;
    HGEMM_CORE(Abase, Bbase, DM, 32);

    #pragma unroll
    for (int mf=0;mf<4;mf++){
        int tr0 = m0 + wm + mf*16 + qr;
        int b0 = tr0 >> 12, n_ = tr0 & 4095;
        #pragma unroll
        for (int nf=0;nf<4;nf++){
            int col = n0 + wn + nf*8 + qc*2;
            int sel = col >> 10;
            int c1  = col & 1023;
            int h = c1 >> 6, d = c1 & 63;
            const float* bias = (sel==0) ? bq : (sel==1) ? bk : bv;
            __half* dst = (sel==0) ? g_qh : (sel==1) ? g_kh : g_vh;
            float bb0 = bias[c1], bb1 = bias[c1+1];
            size_t base0 = (((size_t)(b0*HEADS+h))*SEQ + n_)*DH + d;
            size_t base1 = (((size_t)(b0*HEADS+h))*SEQ + n_ + 8)*DH + d;
            *(__half2*)(dst + base0) = __floats2half2_rn(acc[mf][nf][0]+bb0, acc[mf][nf][1]+bb1);
            *(__half2*)(dst + base1) = __floats2half2_rn(acc[mf][nf][2]+bb0, acc[mf][nf][3]+bb1);
        }
    }
}

// ---------------- output projection GEMM -------------------------------------
__global__ __launch_bounds__(256,2)
void hgemm_out(float* __restrict__ C, const float* __restrict__ bias)
{
    __shared__ __half smh[3*8192];
    const int m0=blockIdx.y*128, n0=blockIdx.x*128;
    GEMM_PREAMBLE();
    const __half* Abase = g_attn + (size_t)m0*DM;
    const __half* Bbase = g_who  + (size_t)n0*DM;
    HGEMM_CORE(Abase, Bbase, DM, 32);

    #pragma unroll
    for (int mf=0;mf<4;mf++){
        #pragma unroll
        for (int nf=0;nf<4;nf++){
            int row = m0 + wm + mf*16 + qr;
            int col = n0 + wn + nf*8 + qc*2;
            float b0 = bias[col], b1 = bias[col+1];
            float2 v0; v0.x=acc[mf][nf][0]+b0; v0.y=acc[mf][nf][1]+b1;
            float2 v1; v1.x=acc[mf][nf][2]+b0; v1.y=acc[mf][nf][3]+b1;
            *(float2*)(C + (size_t)row*DM + col)     = v0;
            *(float2*)(C + (size_t)(row+8)*DM + col) = v1;
        }
    }
}

// ---------------- fused feature GEMM v2: 256 rows/CTA, A double-buffered -----
#define FB_SMEM (34816*2 + 512*4 + 128*4)
__global__ __launch_bounds__(256,1)
void hgemm_feat2()
{
    extern __shared__ __half sh_dyn[];
    __half* B0 = sh_dyn + 16384;
    __half* B1 = sh_dyn + 25600;
    float* rowmax4 = (float*)(sh_dyn + 34816);
    float* diagb   = rowmax4 + 512;

    const int z = blockIdx.y;               // 0: q (fused), 1: k (raw + max + diag)
    const __half* src = z ? g_kh : g_qh;
    const int tid=threadIdx.x, lane=tid&31, wid=tid>>5;
    const int wm=(wid&1)*64, wn=(wid>>1)*72;
    const int qr=lane>>2, qc=lane&3;
    const int lrow=(lane&7)+(lane&8);
    const int lco=lane>>4;
    const size_t tokbase = (size_t)blockIdx.x*256;

#define FA_ISSUE(b) { __half* A0_=sh_dyn+(b)*8192; __half* A1_=A0_+4096; \
    size_t t0_=tokbase+(size_t)(b)*128; \
    _Pragma("unroll") for (int j=0;j<2;j++){ \
        int cid = tid + j*256; int row = cid>>2, cc = cid&3; \
        unsigned sw = (unsigned)((cc^((row>>1)&3))*16); \
        CP16(sptr((char*)A0_ + row*64 + sw), src + (t0_+row)*DH + cc*8); \
        CP16(sptr((char*)A1_ + row*64 + sw), src + (t0_+row)*DH + 32 + cc*8); } }

    #pragma unroll
    for (int j=0;j<5;j++){
        int cid = tid + j*256;
        if (cid < 1152){
            int row = cid>>2, cc = cid&3;
            unsigned sw = (unsigned)((cc^((row>>1)&3))*16);
            CP16(sptr((char*)B0 + row*64 + sw), g_projh + row*DH + cc*8);
            CP16(sptr((char*)B1 + row*64 + sw), g_projh + row*DH + 32 + cc*8);
        }
    }
    FA_ISSUE(0); CPCOMMIT();
    FA_ISSUE(1); CPCOMMIT();
    CPWAIT1();
    __syncthreads();

    float mxk = -3.4e38f;

    for (int b=0; b<2; b++){
        if (b==1){ CPWAIT0(); __syncthreads(); }
        __half* A0 = sh_dyn + b*8192;
        __half* A1 = A0 + 4096;
        const size_t tok0 = tokbase + (size_t)b*128;

        if (tid < 128){
            float s = 0.f;
            #pragma unroll
            for (int st=0; st<2; st++){
                const char* Ab = (const char*)(st ? A1 : A0);
                #pragma unroll
                for (int cc=0;cc<4;cc++){
                    uint4 u = *(const uint4*)(Ab + tid*64 + ((cc^((tid>>1)&3))*16));
                    const __half2* hp = (const __half2*)&u;
                    #pragma unroll
                    for (int p=0;p<4;p++){
                        float2 f = __half22float2(hp[p]);
                        s = fmaf(f.x,f.x,s); s = fmaf(f.y,f.y,s);
                    }
                }
            }
            if (z) g_diagk[tok0 + tid] = DIAG_COEF * s;
            else   diagb[tid] = DIAG_COEF * s;
        }

        float acc[4][9][4];
        #pragma unroll
        for (int i=0;i<4;i++)
            #pragma unroll
            for (int j=0;j<9;j++){acc[i][j][0]=0;acc[i][j][1]=0;acc[i][j][2]=0;acc[i][j][3]=0;}

        #pragma unroll
        for (int k16=0;k16<4;k16++){
            __half* As = (k16<2) ? A0 : A1;
            __half* Bs = (k16<2) ? B0 : B1;
            int kk = k16 & 1;
            unsigned a[4][4];
            #pragma unroll
            for (int mf=0;mf<4;mf++){
                int row = wm + mf*16 + lrow;
                int qd = 2*kk + lco;
                unsigned ad = sptr((char*)As + row*64 + ((qd^((row>>1)&3))*16));
                LDM4(a[mf][0],a[mf][1],a[mf][2],a[mf][3],ad);
            }
            unsigned bfr[9][2];
            #pragma unroll
            for (int p=0;p<4;p++){
                int row = wn + p*16 + lrow;
                int qd = 2*kk + lco;
                unsigned ad = sptr((char*)Bs + row*64 + ((qd^((row>>1)&3))*16));
                unsigned r0,r1,r2,r3; LDM4(r0,r1,r2,r3,ad);
                bfr[2*p][0]=r0; bfr[2*p+1][0]=r1; bfr[2*p][1]=r2; bfr[2*p+1][1]=r3;
            }
            {
                int row8 = wn + 64 + (lane&7);
                int ch = 2*kk + ((lane>>3)&1);
                unsigned ad = sptr((char*)Bs + row8*64 + ((ch^((row8>>1)&3))*16));
                unsigned r0,r1; LDM2(r0,r1,ad);
                bfr[8][0]=r0; bfr[8][1]=r1;
            }
            #pragma unroll
            for (int mf=0;mf<4;mf++)
                #pragma unroll
                for (int nf=0;nf<9;nf++)
                    MMA16(acc[mf][nf], a[mf][0],a[mf][1],a[mf][2],a[mf][3],
                          bfr[nf][0], bfr[nf][1]);
        }

        if (z){
            #pragma unroll
            for (int mf=0;mf<4;mf++){
                #pragma unroll
                for (int h=0;h<2;h++){
                    int row = wm + mf*16 + qr + 8*h;
                    #pragma unroll
                    for (int nf=0;nf<9;nf++){
                        int col = wn + nf*8 + qc*2;
                        float v0 = acc[mf][nf][2*h], v1 = acc[mf][nf][2*h+1];
                        *(__half2*)(g_kp + (tok0+row)*MPX + col) = __floats2half2_rn(v0, v1);
                        if (col   < MF) mxk = fmaxf(mxk, v0);
                        if (col+1 < MF) mxk = fmaxf(mxk, v1);
                    }
                }
            }
            __syncthreads();
            continue;
        }

        // q side: rowmax + exp + store
        float pm[4][2];
        #pragma unroll
        for (int mf=0;mf<4;mf++){ pm[mf][0]=-3.4e38f; pm[mf][1]=-3.4e38f; }
        #pragma unroll
        for (int mf=0;mf<4;mf++)
            #pragma unroll
            for (int nf=0;nf<9;nf++){
                int col = wn + nf*8 + qc*2;
                if (col < MF){
                    pm[mf][0] = fmaxf(pm[mf][0], acc[mf][nf][0]);
                    pm[mf][1] = fmaxf(pm[mf][1], acc[mf][nf][2]);
                }
                if (col+1 < MF){
                    pm[mf][0] = fmaxf(pm[mf][0], acc[mf][nf][1]);
                    pm[mf][1] = fmaxf(pm[mf][1], acc[mf][nf][3]);
                }
            }
        #pragma unroll
        for (int o=1;o<4;o<<=1)
            #pragma unroll
            for (int mf=0;mf<4;mf++){
                pm[mf][0] = fmaxf(pm[mf][0], __shfl_xor_sync(0xffffffffu, pm[mf][0], o));
                pm[mf][1] = fmaxf(pm[mf][1], __shfl_xor_sync(0xffffffffu, pm[mf][1], o));
            }
        if (qc==0){
            #pragma unroll
            for (int mf=0;mf<4;mf++){
                rowmax4[(wm+mf*16+qr  )*4 + (wid>>1)] = pm[mf][0];
                rowmax4[(wm+mf*16+qr+8)*4 + (wid>>1)] = pm[mf][1];
            }
        }
        __syncthreads();

        #pragma unroll
        for (int mf=0;mf<4;mf++){
            #pragma unroll
            for (int h=0;h<2;h++){
                int row = wm + mf*16 + qr + 8*h;
                const float* rm = rowmax4 + row*4;
                float mx = fmaxf(fmaxf(rm[0],rm[1]), fmaxf(rm[2],rm[3]));
                float base = fmaf(-(diagb[row]+mx), LOG2E, LOG2_SCALE_Q);
                #pragma unroll
                for (int nf=0;nf<9;nf++){
                    int col = wn + nf*8 + qc*2;
                    float w0 = (col   < MF) ? (ex2f(fmaf(acc[mf][nf][2*h  ], LOG2E, base)) + KEPS_Q) : 0.f;
                    float w1 = (col+1 < MF) ? (ex2f(fmaf(acc[mf][nf][2*h+1], LOG2E, base)) + KEPS_Q) : 0.f;
                    *(__half2*)(g_qp + (tok0+row)*MPX + col) = __floats2half2_rn(w0, w1);
                }
            }
        }
        __syncthreads();
    }

    if (z){
        #pragma unroll
        for (int o=16;o;o>>=1) mxk = fmaxf(mxk, __shfl_xor_sync(0xffffffffu, mxk, o));
        if (lane==0) rowmax4[wid] = mxk;
        __syncthreads();
        if (tid==0){
            float m = rowmax4[0];
            #pragma unroll
            for (int w=1;w<8;w++) m = fmaxf(m, rowmax4[w]);
            atomicMax(&g_kmax_bits, enc_f(m));
        }
    }
#undef FA_ISSUE
}

// ---------------- fused prep ----------------
#define N4_X (ROWS*DM/4)
#define N4_W (DM*DM/4)
#define N4_P (384*DH/4)
#define N4_ALL (N4_X + 4*N4_W + N4_P)
__global__ void prep_all(const float* __restrict__ x,  const float* __restrict__ Wq,
                         const float* __restrict__ Wk, const float* __restrict__ Wv,
                         const float* __restrict__ Wo, const float* __restrict__ proj)
{
    long i = (long)blockIdx.x*256 + threadIdx.x;
    if (i == 0) g_kmax_bits = 0u;
    if (i < N4_X){
        float4 v = ((const float4*)x)[i];
        ((__half2*)g_xh)[i*2]   = __floats2half2_rn(v.x, v.y);
        ((__half2*)g_xh)[i*2+1] = __floats2half2_rn(v.z, v.w);
        return;
    }
    i -= N4_X;
    if (i < 4L*N4_W){
        int w = (int)(i / N4_W); long j = i % N4_W;
        const float* src = (w==0)?Wq:(w==1)?Wk:(w==2)?Wv:Wo;
        __half* dst = (w<3) ? (g_wh3 + (size_t)w*DM*DM) : g_who;
        float4 v = ((const float4*)src)[j];
        ((__half2*)dst)[j*2]   = __floats2half2_rn(v.x, v.y);
        ((__half2*)dst)[j*2+1] = __floats2half2_rn(v.z, v.w);
        return;
    }
    i -= 4L*N4_W;
    if (i < N4_P){
        long e = i*4;
        #pragma unroll
        for (int j=0;j<4;j++){
            long m = (e+j)/DH, d = (e+j)%DH;
            g_projh[e+j] = (m < MF) ? __float2half(proj[m*DH+d]*NORMALIZER)
                                    : __float2half(0.f);
        }
    }
}

// ---------------- chunk sums via fp16 MMA (exp fused in) ---------------------
#define CS_SMEM ((128*296 + 128*72)*2)
extern __shared__ __half sh_dyn2[];
__global__ __launch_bounds__(256)
void chunk_sums_mma()
{
    __half* Kt = sh_dyn2;
    __half* Vt = sh_dyn2 + 128*296;
    const int tid=threadIdx.x, lane=tid&31, wid=tid>>5;
    const int blk=blockIdx.x;
    const size_t tok0=(size_t)blk*CHK;
    const int qr=lane>>2, qc=lane&3;

    #pragma unroll
    for (int j=0;j<18;j++){
        int cid = tid + j*256; int row = cid/36, c = cid%36;
        CP16(sptr(Kt + row*296 + c*8), g_kp + (tok0+row)*MPX + c*8);
    }
    #pragma unroll
    for (int j=0;j<4;j++){
        int cid = tid + j*256; int row = cid>>3, c = cid&7;
        CP16(sptr(Vt + row*72 + c*8), g_vh + (tok0+row)*DH + c*8);
    }
    CPCOMMIT(); CPWAIT0();
    __syncthreads();

    // fused exp feature map on raw Kt (in smem) + write exp'd kp back to global
    {
        const float mxk = dec_f(g_kmax_bits);
        int row = tid >> 1, half = tid & 1;
        float dg = g_diagk[tok0 + row];
        float base = fmaf(-(dg + mxk), LOG2E, LOG2_SCALE_K);
        uint4* rp = (uint4*)(Kt + row*296 + half*144);
        __half* gp = g_kp + (tok0+row)*MPX + half*144;
        #pragma unroll
        for (int i4=0;i4<18;i4++){
            uint4 u = rp[i4];
            float v[8]; unpack8(u, v);
            float w[8];
            #pragma unroll
            for (int j=0;j<8;j++){
                int col = half*144 + i4*8 + j;
                w[j] = (col < MF) ? (ex2f(fmaf(v[j], LOG2E, base)) + KEPS_K) : 0.f;
            }
            uint4 o = pack8(w);
            rp[i4] = o;
            *(uint4*)(gp + i4*8) = o;
        }
    }
    if (tid < 128){
        __half* vr = Vt + tid*72;
        vr[64] = __float2half(1.f);
        #pragma unroll
        for (int j=65;j<72;j++) vr[j] = __float2half(0.f);
    }
    __syncthreads();

    const int nfr = (wid<2) ? 3 : 2;
    int mfs[3]; mfs[0]=wid; mfs[1]=wid+8; mfs[2]=16+wid;
    float acc[3][9][4];
    #pragma unroll
    for(int i=0;i<3;i++)
        #pragma unroll
        for(int j=0;j<9;j++){acc[i][j][0]=0;acc[i][j][1]=0;acc[i][j][2]=0;acc[i][j][3]=0;}

    for (int ks=0;ks<8;ks++){
        int k0 = ks*16;
        int trow = k0 + (lane&7) + ((lane&16)>>1);
        unsigned bf[9][2];
        #pragma unroll
        for (int bi=0;bi<4;bi++){
            unsigned ad = sptr(Vt + trow*72 + bi*16 + (lane&8));
            unsigned r0,r1,r2,r3; LDM4T(r0,r1,r2,r3,ad);
            bf[2*bi][0]=r0; bf[2*bi][1]=r2; bf[2*bi+1][0]=r1; bf[2*bi+1][1]=r3;
        }
        {
            unsigned ad = sptr(Vt + (k0 + (lane&15))*72 + 64);
            unsigned r0,r1; LDM2T(r0,r1,ad);
            bf[8][0]=r0; bf[8][1]=r1;
        }
        for (int fi=0; fi<nfr; fi++){
            unsigned ad = sptr(Kt + trow*296 + mfs[fi]*16 + (lane&8));
            unsigned a0,a1,a2,a3; LDM4T(a0,a1,a2,a3,ad);
            #pragma unroll
            for (int nf=0;nf<9;nf++)
                MMA16(acc[fi][nf], a0,a1,a2,a3, bf[nf][0], bf[nf][1]);
        }
    }

    for (int fi=0; fi<nfr; fi++){
        int m0 = mfs[fi]*16;
        #pragma unroll
        for (int nf=0;nf<8;nf++){
            int col = nf*8 + qc*2;
            *(__half2*)(g_csh + ((size_t)blk*MPX + m0+qr)*DH + col)   = __floats2half2_rn(acc[fi][nf][0], acc[fi][nf][1]);
            *(__half2*)(g_csh + ((size_t)blk*MPX + m0+qr+8)*DH + col) = __floats2half2_rn(acc[fi][nf][2], acc[fi][nf][3]);
        }
        if (qc==0){
            g_zsh[(size_t)blk*MPX + m0+qr]   = __float2half(acc[fi][8][0]);
            g_zsh[(size_t)blk*MPX + m0+qr+8] = __float2half(acc[fi][8][2]);
        }
    }
}

// ---------------- parallel exclusive scan (uint2 + prefetch) -----------------
__global__ __launch_bounds__(256)
void scan_par()
{
    int bh = blockIdx.y;
    if (blockIdx.x < 18){
        int l = blockIdx.x*256 + threadIdx.x;
        uint2* base = (uint2*)(g_csh + (size_t)bh*NC*MPX*DH) + l;
        const int stride = MPX*DH/4;
        float s0=0.f,s1=0.f,s2=0.f,s3=0.f;
        uint2 cur = base[0];
        #pragma unroll
        for (int c=0;c<NC;c++){
            uint2 nxt = make_uint2(0,0);
            if (c+1<NC) nxt = base[(size_t)(c+1)*stride];
            float2 t0 = __half22float2(*(__half2*)&cur.x);
            float2 t1 = __half22float2(*(__half2*)&cur.y);
            uint2 o;
            *(__half2*)&o.x = __floats2half2_rn(s0, s1);
            *(__half2*)&o.y = __floats2half2_rn(s2, s3);
            base[(size_t)c*stride] = o;
            s0 += t0.x; s1 += t0.y; s2 += t1.x; s3 += t1.y;
            cur = nxt;
        }
    } else {
        if (threadIdx.x < 72){
            uint2* base = (uint2*)(g_zsh + (size_t)bh*NC*MPX) + threadIdx.x;
            const int stride = MPX/4;
            float s0=0.f,s1=0.f,s2=0.f,s3=0.f;
            uint2 cur = base[0];
            #pragma unroll
            for (int c=0;c<NC;c++){
                uint2 nxt = make_uint2(0,0);
                if (c+1<NC) nxt = base[(size_t)(c+1)*stride];
                float2 t0 = __half22float2(*(__half2*)&cur.x);
                float2 t1 = __half22float2(*(__half2*)&cur.y);
                uint2 o;
                *(__half2*)&o.x = __floats2half2_rn(s0, s1);
                *(__half2*)&o.y = __floats2half2_rn(s2, s3);
                base[(size_t)c*stride] = o;
                s0 += t0.x; s1 += t0.y; s2 += t1.x; s3 += t1.y;
                cur = nxt;
            }
        }
    }
}

// ---------------- out_chunk via fp16 MMA --------------------------------------
#define OC_STAGE 10496
#define OC_VT 20992
#define OC_SMEM ((20992 + 128*72)*2)
__global__ __launch_bounds__(256)
void out_chunk_h()
{
    __half* Am = sh_dyn2;
    __half* Vt = sh_dyn2 + OC_VT;
    const int tid=threadIdx.x, lane=tid&31, wid=tid>>5;
    const int blk=blockIdx.x, bh=blk>>5, c=blk&31;
    const size_t tok0=(size_t)blk*CHK;
    const int qr=lane>>2, qc=lane&3;
    const int lrow=(lane&7)+(lane&8);
    const int lco=lane>>4;
    const __half ceps_h = __float2half(KSCALE*CEPS);

    #pragma unroll
    for (int j=0;j<4;j++){
        int cid = tid + j*256; int row = cid>>3, cc = cid&7;
        CP16(sptr(Vt + row*72 + cc*8), g_vh + (tok0+row)*DH + cc*8);
    }

    float accA[16][4];
    float accO[9][4];
    #pragma unroll
    for(int i=0;i<16;i++){accA[i][0]=0;accA[i][1]=0;accA[i][2]=0;accA[i][3]=0;}
    #pragma unroll
    for(int i=0;i<9;i++){accO[i][0]=0;accO[i][1]=0;accO[i][2]=0;accO[i][3]=0;}

#define OCH_ISSUE(t) { int s_=(t)&1; \
    __half* Qs_=sh_dyn2+s_*OC_STAGE; __half* Ks_=Qs_+4096; __half* Ss_=Qs_+8192; \
    _Pragma("unroll") for(int h=0;h<2;h++){ \
      int id=tid+h*256; int row=id>>2, cc=id&3; \
      unsigned sw=(unsigned)((cc^((row>>1)&3))*16); \
      CP16(sptr((char*)Qs_+row*64+sw), g_qp+(tok0+row)*MPX+(t)*32+cc*8); \
      CP16(sptr((char*)Ks_+row*64+sw), g_kp+(tok0+row)*MPX+(t)*32+cc*8); } \
    { int row=tid>>3, cc=tid&7; \
      CP16(sptr(Ss_+row*72+cc*8), g_csh+((size_t)blk*MPX+(t)*32+row)*DH+cc*8); } \
    if (tid<32){ __half* sr=Ss_+tid*72; sr[64]=g_zsh[(size_t)blk*MPX+(t)*32+tid]; \
      sr[65]=ceps_h; \
      _Pragma("unroll") for(int j=66;j<72;j++) sr[j]=__float2half(0.f); } \
    CPCOMMIT(); }

    OCH_ISSUE(0);
    for (int t=0;t<9;t++){
        if (t+1<9) OCH_ISSUE(t+1);
        if (t<8) CPWAIT1(); else CPWAIT0();
        __syncthreads();
        __half* Qs = sh_dyn2 + (t&1)*OC_STAGE;
        __half* Ks = Qs + 4096;
        __half* Ss = Qs + 8192;
        #pragma unroll
        for (int k16=0;k16<2;k16++){
            unsigned a[4];
            {
                int row = wid*16 + lrow;
                int qd = 2*k16 + lco;
                unsigned ad = sptr((char*)Qs + row*64 + ((qd^((row>>1)&3))*16));
                LDM4(a[0],a[1],a[2],a[3],ad);
            }
            #pragma unroll
            for (int p=0;p<8;p++){
                int row = p*16 + lrow;
                int qd = 2*k16 + lco;
                unsigned ad = sptr((char*)Ks + row*64 + ((qd^((row>>1)&3))*16));
                unsigned r0,r1,r2,r3; LDM4(r0,r1,r2,r3,ad);
                MMA16(accA[2*p],  a[0],a[1],a[2],a[3], r0, r2);
                MMA16(accA[2*p+1],a[0],a[1],a[2],a[3], r1, r3);
            }
            {
                int trow = k16*16 + (lane&7) + ((lane&16)>>1);
                unsigned bf[9][2];
                #pragma unroll
                for (int bi=0;bi<4;bi++){
                    unsigned ad = sptr(Ss + trow*72 + bi*16 + (lane&8));
                    unsigned r0,r1,r2,r3; LDM4T(r0,r1,r2,r3,ad);
                    bf[2*bi][0]=r0; bf[2*bi][1]=r2; bf[2*bi+1][0]=r1; bf[2*bi+1][1]=r3;
                }
                {
                    unsigned ad = sptr(Ss + (k16*16 + (lane&15))*72 + 64);
                    unsigned r0,r1; LDM2T(r0,r1,ad);
                    bf[8][0]=r0; bf[8][1]=r1;
                }
                #pragma unroll
                for (int nf=0;nf<9;nf++)
                    MMA16(accO[nf], a[0],a[1],a[2],a[3], bf[nf][0], bf[nf][1]);
            }
        }
        __syncthreads();
    }

    if (tid < 128){
        __half* vr = Vt + tid*72;
        vr[64] = __float2half(1.f);
        #pragma unroll
        for (int j=65;j<72;j++) vr[j] = __float2half(0.f);
    }
    #pragma unroll
    for (int nf=0;nf<16;nf++){
        int col = nf*8 + qc*2;
        int r0 = wid*16 + qr, r1 = r0 + 8;
        *(__half2*)(Am + r0*136 + col) = __floats2half2_rn(
            (col <= r0) ? accA[nf][0] : 0.f, (col+1 <= r0) ? accA[nf][1] : 0.f);
        *(__half2*)(Am + r1*136 + col) = __floats2half2_rn(
            (col <= r1) ? accA[nf][2] : 0.f, (col+1 <= r1) ? accA[nf][3] : 0.f);
    }
    __syncthreads();

    for (int kt=0;kt<8;kt++){
        unsigned a[4];
        {
            int row = wid*16 + lrow;
            unsigned ad = sptr((char*)Am + row*272 + kt*32 + lco*16);
            LDM4(a[0],a[1],a[2],a[3],ad);
        }
        int trow = kt*16 + (lane&7) + ((lane&16)>>1);
        unsigned bf[9][2];
        #pragma unroll
        for (int bi=0;bi<4;bi++){
            unsigned ad = sptr(Vt + trow*72 + bi*16 + (lane&8));
            unsigned r0,r1,r2,r3; LDM4T(r0,r1,r2,r3,ad);
            bf[2*bi][0]=r0; bf[2*bi][1]=r2; bf[2*bi+1][0]=r1; bf[2*bi+1][1]=r3;
        }
        {
            unsigned ad = sptr(Vt + (kt*16 + (lane&15))*72 + 64);
            unsigned r0,r1; LDM2T(r0,r1,ad);
            bf[8][0]=r0; bf[8][1]=r1;
        }
        #pragma unroll
        for (int nf=0;nf<9;nf++)
            MMA16(accO[nf], a[0],a[1],a[2],a[3], bf[nf][0], bf[nf][1]);
    }

    float d0 = accO[8][0] + accO[8][1];
    float d1 = accO[8][2] + accO[8][3];
    d0 = __shfl_sync(0xffffffffu, d0, lane & ~3);
    d1 = __shfl_sync(0xffffffffu, d1, lane & ~3);
    float inv0 = 1.f/d0, inv1 = 1.f/d1;

    int b = bh >> 4, h = bh & 15;
    int n0 = c*CHK + wid*16;
    #pragma unroll
    for (int nf=0;nf<8;nf++){
        int col = h*64 + nf*8 + qc*2;
        __half2* o0 = (__half2*)(g_attn + ((size_t)(b*SEQ + n0 + qr))*DM + col);
        __half2* o1 = (__half2*)(g_attn + ((size_t)(b*SEQ + n0 + qr + 8))*DM + col);
        *o0 = __floats2half2_rn(accO[nf][0]*inv0, accO[nf][1]*inv0);
        *o1 = __floats2half2_rn(accO[nf][2]*inv1, accO[nf][3]*inv1);
    }
#undef OCH_ISSUE
}

// ---------------- launch ------------------------------------------------------
extern "C" void kernel_launch(void* const* d_in, const int* in_sizes, int n_in,
                              void* d_out, int out_size)
{
    (void)in_sizes; (void)n_in; (void)out_size;
    const float* x    = (const float*)d_in[0];
    const float* Wq   = (const float*)d_in[1];
    const float* bq   = (const float*)d_in[2];
    const float* Wk   = (const float*)d_in[3];
    const float* bk   = (const float*)d_in[4];
    const float* Wv   = (const float*)d_in[5];
    const float* bv   = (const float*)d_in[6];
    const float* Wo   = (const float*)d_in[7];
    const float* bo   = (const float*)d_in[8];
    const float* proj = (const float*)d_in[9];
    float* out = (float*)d_out;

    cudaFuncSetAttribute(chunk_sums_mma, cudaFuncAttributeMaxDynamicSharedMemorySize, CS_SMEM);
    cudaFuncSetAttribute(out_chunk_h, cudaFuncAttributeMaxDynamicSharedMemorySize, OC_SMEM);
    cudaFuncSetAttribute(hgemm_feat2, cudaFuncAttributeMaxDynamicSharedMemorySize, FB_SMEM);

    prep_all<<<(N4_ALL+255)/256, 256>>>(x, Wq, Wk, Wv, Wo, proj);

    dim3 gq(3*DM/128, ROWS/128);   // (24, 64)
    hgemm_qkv<<<gq,256>>>(bq, bk, bv);

    dim3 gfeat(TOK/256, 2);
    hgemm_feat2<<<gfeat,256,FB_SMEM>>>();

    chunk_sums_mma<<<BH*NC,256,CS_SMEM>>>();
    dim3 gsc(19, BH);
    scan_par<<<gsc,256>>>();
    out_chunk_h<<<BH*NC,256,OC_SMEM>>>();

    dim3 go(DM/128, ROWS/128);
    hgemm_out<<<go,256>>>(out, bo);
}